// round 10
// baseline (speedup 1.0000x reference)
#include <cuda_runtime.h>
#include <cuda_bf16.h>
#include <math.h>
#include <stdint.h>

#define LOG_EPS 2.220446049250313e-16f

// ---------------- static scratch ----------------
__device__ float g_h1[1024 * 256 * 64];     // conv1 out [patch][64]
__device__ float g_h2[1024 * 16 * 256];     // conv2 out [patch][256] == fc input
__device__ float g_fcp[8 * 1024 * 512];     // fc split-K partials
__device__ float g_emb[1024 * 512];
__device__ float g_gw[64 * 6];
__device__ int g_gidx[64 * 6];
__device__ __nv_bfloat16 g_w1bf[2][64][256];     // conv1 W [hi/lo][n][k]
__device__ __nv_bfloat16 g_w2bf[2][256][1024];   // conv2 W [hi/lo][n][k]
__device__ __nv_bfloat16 g_fcwbf[2][512][4096];  // fc W    [hi/lo][n][k]
__device__ __nv_bfloat16 g_ewbf[2][6][512][512]; // expert W [hi/lo][e][n][k]

// ---------------- helpers ----------------
__device__ __forceinline__ int clamp_topk(const int* topk) {
    int k = *topk;
    if (k < 1 || k > 6) {
        float fv = __int_as_float(k);
        if (fv >= 1.0f && fv <= 6.0f) k = (int)fv; else k = 2;
    }
    return k;
}
__device__ __forceinline__ float gelu_exact(float t) {
    return 0.5f * t * (1.0f + erff(t * 0.7071067811865476f));
}
__device__ __forceinline__ uint32_t smem_u32(const void* p) {
    uint32_t a;
    asm("{ .reg .u64 t; cvta.to.shared.u64 t, %1; cvt.u32.u64 %0, t; }" : "=r"(a) : "l"(p));
    return a;
}
__device__ __forceinline__ void ldmx4(uint32_t* r, uint32_t addr) {
    asm volatile("ldmatrix.sync.aligned.m8n8.x4.shared.b16 {%0,%1,%2,%3}, [%4];"
        : "=r"(r[0]), "=r"(r[1]), "=r"(r[2]), "=r"(r[3]) : "r"(addr));
}
__device__ __forceinline__ void ldmx2(uint32_t* r, uint32_t addr) {
    asm volatile("ldmatrix.sync.aligned.m8n8.x2.shared.b16 {%0,%1}, [%2];"
        : "=r"(r[0]), "=r"(r[1]) : "r"(addr));
}
__device__ __forceinline__ void mma16816(float* d, const uint32_t* a, const uint32_t* b) {
    asm volatile("mma.sync.aligned.m16n8k16.row.col.f32.bf16.bf16.f32 "
        "{%0,%1,%2,%3}, {%4,%5,%6,%7}, {%8,%9}, {%0,%1,%2,%3};"
        : "+f"(d[0]), "+f"(d[1]), "+f"(d[2]), "+f"(d[3])
        : "r"(a[0]), "r"(a[1]), "r"(a[2]), "r"(a[3]), "r"(b[0]), "r"(b[1]));
}
__device__ __forceinline__ void cvt4(const float* f, uint2& hi, uint2& lo) {
    union { __nv_bfloat16 b[4]; uint2 u; } H, L;
#pragma unroll
    for (int q = 0; q < 4; q++) {
        H.b[q] = __float2bfloat16(f[q]);
        L.b[q] = __float2bfloat16(f[q] - __bfloat162float(H.b[q]));
    }
    hi = H.u; lo = L.u;
}
__device__ __forceinline__ void cpa16(uint32_t dst, const void* src) {
    asm volatile("cp.async.cg.shared.global [%0], [%1], 16;" :: "r"(dst), "l"(src) : "memory");
}
#define CPA_COMMIT() asm volatile("cp.async.commit_group;" ::: "memory")
#define CPA_WAIT0()  asm volatile("cp.async.wait_group 0;" ::: "memory")
#define BAR_SYNC(id, cnt)   asm volatile("bar.sync %0, %1;" :: "r"(id), "r"(cnt) : "memory")
#define BAR_ARRIVE(id, cnt) asm volatile("bar.arrive %0, %1;" :: "r"(id), "r"(cnt) : "memory")

// ---------------- weight prep ----------------
__global__ void k_prep_w1(const float* __restrict__ w) {
    int idx = blockIdx.x * 256 + threadIdx.x;
    if (idx >= 64 * 256) return;
    int o = idx >> 8, r = idx & 255;
    int c = r >> 4, i = (r >> 2) & 3, j = r & 3;
    int k = i * 64 + j * 16 + c;
    float f = w[idx];
    __nv_bfloat16 hi = __float2bfloat16(f);
    g_w1bf[0][o][k] = hi;
    g_w1bf[1][o][k] = __float2bfloat16(f - __bfloat162float(hi));
}
__global__ void k_prep_w2(const float* __restrict__ w) {
    int idx = blockIdx.x * 256 + threadIdx.x;
    if (idx >= 256 * 1024) return;
    int o = idx >> 10, k = idx & 1023;
    int cin = k & 63, ij = k >> 6;
    float f = w[o * 1024 + cin * 16 + ij];
    __nv_bfloat16 hi = __float2bfloat16(f);
    g_w2bf[0][o][k] = hi;
    g_w2bf[1][o][k] = __float2bfloat16(f - __bfloat162float(hi));
}
__global__ __launch_bounds__(256) void k_prep_fcw(const float* __restrict__ w) {
    __shared__ float ts[32][33];
    int tid = threadIdx.x;
    int kb = blockIdx.x * 32, nb = blockIdx.y * 32;
#pragma unroll
    for (int it = 0; it < 4; it++) {
        int r = it * 8 + (tid >> 5), c = tid & 31;
        ts[r][c] = w[(size_t)(kb + r) * 512 + nb + c];
    }
    __syncthreads();
    int h = tid >> 7, n = (tid >> 2) & 31, q = tid & 3;
    union { __nv_bfloat16 b[8]; uint4 u; } U;
#pragma unroll
    for (int i = 0; i < 8; i++) {
        float f = ts[q * 8 + i][n];
        __nv_bfloat16 hi = __float2bfloat16(f);
        U.b[i] = h ? __float2bfloat16(f - __bfloat162float(hi)) : hi;
    }
    *(uint4*)&g_fcwbf[h][nb + n][kb + q * 8] = U.u;
}
__global__ __launch_bounds__(256) void k_prep_ew(const float* __restrict__ w) {
    __shared__ float ts[32][33];
    int tid = threadIdx.x;
    int kb = blockIdx.x * 32, nb = blockIdx.y * 32, e = blockIdx.z;
    const float* we = w + (size_t)e * 262144;
#pragma unroll
    for (int it = 0; it < 4; it++) {
        int r = it * 8 + (tid >> 5), c = tid & 31;
        ts[r][c] = we[(size_t)(kb + r) * 512 + nb + c];
    }
    __syncthreads();
    int h = tid >> 7, n = (tid >> 2) & 31, q = tid & 3;
    union { __nv_bfloat16 b[8]; uint4 u; } U;
#pragma unroll
    for (int i = 0; i < 8; i++) {
        float f = ts[q * 8 + i][n];
        __nv_bfloat16 hi = __float2bfloat16(f);
        U.b[i] = h ? __float2bfloat16(f - __bfloat162float(hi)) : hi;
    }
    *(uint4*)&g_ewbf[h][e][nb + n][kb + q * 8] = U.u;
}

// ---------------- conv1: warp-specialized. M-tile 128, N=64, K=4x64 chunks ----------------
// smem: A bf16 ring buf{0,1} [0,73728) (per buf 36864: hi 18432 + lo 18432), B resident [73728,147456)
// producers = warps 0-3 (128 thr), consumers = warps 4-11 (256 thr)
#define C1_SMEM 147456
#define BARF0 1
#define BARE0 3
#define BARC  5
__global__ __launch_bounds__(384, 1) void k_conv1_mma(const float* __restrict__ x,
                                                      const float* __restrict__ cbp,
                                                      const float* __restrict__ lg,
                                                      const float* __restrict__ lb) {
    extern __shared__ __align__(16) unsigned char sm[];
    uint32_t sb = smem_u32(sm);
    int tid = threadIdx.x, lane = tid & 31, wid = tid >> 5;
    int p0 = blockIdx.x * 128;
    const float* xb = x + (size_t)(p0 >> 8) * 65536;
    int pbase = p0 & 255;

    // B resident: 4 chunks x 2 halves x 64 rows x 8 uint4 = 4096 uint4
    for (int g = tid; g < 4096; g += 384) {
        int chunk = g >> 10, h = (g >> 9) & 1, rem = g & 511;
        int o = rem >> 3, q = rem & 7;
        uint4 v = *(const uint4*)((const unsigned char*)g_w1bf + h * 32768 + o * 512 + chunk * 128 + q * 16);
        *(uint4*)(sm + 73728 + chunk * 18432 + h * 9216 + o * 144 + q * 16) = v;
    }
    __syncthreads();

    if (wid < 4) {
        // ---- producer: load x, convert hi/lo, fill ring ----
        int ptid = tid;  // 0..127
        for (int kc = 0; kc < 4; kc++) {
            if (kc >= 2) BAR_SYNC(BARE0 + (kc & 1), 384);
            uint32_t base = (kc & 1) * 36864;
            float4 v[16];
#pragma unroll
            for (int it = 0; it < 16; it++) {
                int g = it * 128 + ptid;
                int m = g >> 4, q = g & 15;
                int pm = pbase + m;
                int ph = pm >> 4, pw = pm & 15;
                v[it] = *(const float4*)(xb + ((ph * 4 + kc) * 64 + pw * 4 + (q >> 2)) * 16 + (q & 3) * 4);
            }
#pragma unroll
            for (int it = 0; it < 16; it++) {
                int g = it * 128 + ptid;
                int m = g >> 4, q = g & 15;
                uint2 hi, lo; cvt4((const float*)&v[it], hi, lo);
                *(uint2*)(sm + base + m * 144 + q * 8) = hi;
                *(uint2*)(sm + base + 18432 + m * 144 + q * 8) = lo;
            }
            BAR_ARRIVE(BARF0 + (kc & 1), 384);
        }
    } else {
        // ---- consumer: pure ldmatrix + MMA ----
        int cw = wid - 4, wm = cw >> 1, wn = cw & 1;
        float acc[2][4][4];
#pragma unroll
        for (int a = 0; a < 2; a++)
#pragma unroll
            for (int b = 0; b < 4; b++)
#pragma unroll
                for (int c = 0; c < 4; c++) acc[a][b][c] = 0.0f;

        for (int kc = 0; kc < 4; kc++) {
            BAR_SYNC(BARF0 + (kc & 1), 384);
            uint32_t aHi = sb + (kc & 1) * 36864 + (wm * 32 + (lane & 15)) * 144 + (lane >> 4) * 16;
            uint32_t bB = sb + 73728 + kc * 18432 + (wn * 32 + (lane & 7)) * 144 + ((lane >> 3) & 1) * 16;
#pragma unroll
            for (int ks = 0; ks < 4; ks++) {
                uint32_t ah[2][4], al[2][4];
                ldmx4(ah[0], aHi + ks * 32);
                ldmx4(ah[1], aHi + 2304 + ks * 32);
                ldmx4(al[0], aHi + 18432 + ks * 32);
                ldmx4(al[1], aHi + 18432 + 2304 + ks * 32);
#pragma unroll
                for (int nt = 0; nt < 4; nt++) {
                    uint32_t bh[2], bl[2];
                    ldmx2(bh, bB + nt * 1152 + ks * 32);
                    ldmx2(bl, bB + 9216 + nt * 1152 + ks * 32);
#pragma unroll
                    for (int mt = 0; mt < 2; mt++) {
                        mma16816(acc[mt][nt], ah[mt], bh);
                        mma16816(acc[mt][nt], ah[mt], bl);
                        mma16816(acc[mt][nt], al[mt], bh);
                    }
                }
            }
            BAR_ARRIVE(BARE0 + (kc & 1), 384);
        }

        // epilogue: bias + LN(64, cross-wn via smem) + GELU (consumers only)
        float* red = (float*)sm;  // buffer 0 region, free (last MMA used buffer 1)
        int r0 = lane >> 2, cbs = (lane & 3) * 2;
#pragma unroll
        for (int mt = 0; mt < 2; mt++)
#pragma unroll
            for (int half = 0; half < 2; half++) {
                float s = 0.0f, s2 = 0.0f;
#pragma unroll
                for (int nt = 0; nt < 4; nt++)
#pragma unroll
                    for (int c = 0; c < 2; c++) {
                        int col = wn * 32 + nt * 8 + cbs + c;
                        float t = acc[mt][nt][half * 2 + c] + cbp[col];
                        acc[mt][nt][half * 2 + c] = t;
                        s += t; s2 += t * t;
                    }
                s += __shfl_xor_sync(0xffffffffu, s, 1);
                s += __shfl_xor_sync(0xffffffffu, s, 2);
                s2 += __shfl_xor_sync(0xffffffffu, s2, 1);
                s2 += __shfl_xor_sync(0xffffffffu, s2, 2);
                int row = wm * 32 + mt * 16 + half * 8 + r0;
                if ((lane & 3) == 0) {
                    red[row * 4 + wn * 2 + 0] = s;
                    red[row * 4 + wn * 2 + 1] = s2;
                }
            }
        BAR_SYNC(BARC, 256);
#pragma unroll
        for (int mt = 0; mt < 2; mt++)
#pragma unroll
            for (int half = 0; half < 2; half++) {
                int row = wm * 32 + mt * 16 + half * 8 + r0;
                float s = red[row * 4 + 0] + red[row * 4 + 2];
                float s2 = red[row * 4 + 1] + red[row * 4 + 3];
                float mean = s * (1.0f / 64.0f);
                float var = s2 * (1.0f / 64.0f) - mean * mean;
                float rstd = rsqrtf(var + 1e-5f);
                float* dst = g_h1 + (size_t)(p0 + row) * 64;
#pragma unroll
                for (int nt = 0; nt < 4; nt++)
#pragma unroll
                    for (int c = 0; c < 2; c++) {
                        int col = wn * 32 + nt * 8 + cbs + c;
                        float t = (acc[mt][nt][half * 2 + c] - mean) * rstd * lg[col] + lb[col];
                        dst[col] = gelu_exact(t);
                    }
            }
    }
}

// ---------------- conv2: M=16384 (tile 128), N=256, K=1024, pipelined ----------------
#define C2_SMEM 221184
__global__ __launch_bounds__(256) void k_conv2_mma(const float* __restrict__ cbp,
                                                   const float* __restrict__ lg,
                                                   const float* __restrict__ lb) {
    extern __shared__ __align__(16) unsigned char sm[];
    uint32_t sb = smem_u32(sm);
    int tid = threadIdx.x, lane = tid & 31, wid = tid >> 5;
    int wm = wid & 3, wn = wid >> 2;
    int p0 = blockIdx.x * 128;

#define C2_CP_B(kc, buf) do { \
    _Pragma("unroll") \
    for (int it = 0; it < 16; it++) { \
        int g = it * 256 + tid; int h = g >> 11, rem = g & 2047; \
        int n = rem >> 3, q = rem & 7; \
        cpa16(sb + 73728 + (buf) * 73728 + h * 36864 + n * 144 + q * 16, \
              (const unsigned char*)g_w2bf + h * 524288 + n * 2048 + (kc) * 128 + q * 16); \
    } CPA_COMMIT(); } while (0)

    float4 f4[8];
#define C2_LOAD_A(kc) do { \
    int i_ = (kc) >> 2, j_ = (kc) & 3; \
    _Pragma("unroll") \
    for (int it = 0; it < 8; it++) { \
        int g = it * 256 + tid; int m = g >> 4, q = g & 15; \
        int pg = p0 + m; int btq = pg >> 4, qp = pg & 15; \
        int qh = qp >> 2, qw = qp & 3; \
        f4[it] = *(const float4*)(g_h1 + ((size_t)btq * 256 + (qh * 4 + i_) * 16 + (qw * 4 + j_)) * 64 + q * 4); \
    } } while (0)
#define C2_STORE_A(buf) do { \
    _Pragma("unroll") \
    for (int it = 0; it < 8; it++) { \
        int g = it * 256 + tid; int m = g >> 4, q = g & 15; \
        uint2 hi, lo; cvt4((const float*)&f4[it], hi, lo); \
        *(uint2*)(sm + (buf) * 36864 + m * 144 + q * 8) = hi; \
        *(uint2*)(sm + (buf) * 36864 + 18432 + m * 144 + q * 8) = lo; \
    } } while (0)

    C2_CP_B(0, 0);
    C2_LOAD_A(0);
    C2_STORE_A(0);
    CPA_WAIT0();
    __syncthreads();

    float acc[2][16][4];
#pragma unroll
    for (int a = 0; a < 2; a++)
#pragma unroll
        for (int b = 0; b < 16; b++)
#pragma unroll
            for (int c = 0; c < 4; c++) acc[a][b][c] = 0.0f;

    for (int kc = 0; kc < 16; kc++) {
        if (kc < 15) {
            C2_CP_B(kc + 1, (kc + 1) & 1);
            C2_LOAD_A(kc + 1);
        }
        uint32_t aHi = sb + (kc & 1) * 36864 + (wm * 32 + (lane & 15)) * 144 + (lane >> 4) * 16;
        uint32_t bB = sb + 73728 + (kc & 1) * 73728 + (wn * 128 + (lane & 7)) * 144 + ((lane >> 3) & 1) * 16;
#pragma unroll
        for (int ks = 0; ks < 4; ks++) {
            uint32_t ah[2][4], al[2][4];
            ldmx4(ah[0], aHi + ks * 32);
            ldmx4(ah[1], aHi + 2304 + ks * 32);
            ldmx4(al[0], aHi + 18432 + ks * 32);
            ldmx4(al[1], aHi + 18432 + 2304 + ks * 32);
#pragma unroll
            for (int nt = 0; nt < 16; nt++) {
                uint32_t bh[2], bl[2];
                ldmx2(bh, bB + nt * 1152 + ks * 32);
                ldmx2(bl, bB + 36864 + nt * 1152 + ks * 32);
#pragma unroll
                for (int mt = 0; mt < 2; mt++) {
                    mma16816(acc[mt][nt], ah[mt], bh);
                    mma16816(acc[mt][nt], ah[mt], bl);
                    mma16816(acc[mt][nt], al[mt], bh);
                }
            }
        }
        if (kc < 15) {
            C2_STORE_A((kc + 1) & 1);
            CPA_WAIT0();
            __syncthreads();
        }
    }
    __syncthreads();

    float* red = (float*)sm;
    int r0 = lane >> 2, cbs = (lane & 3) * 2;
#pragma unroll
    for (int mt = 0; mt < 2; mt++)
#pragma unroll
        for (int half = 0; half < 2; half++) {
            float s = 0.0f, s2 = 0.0f;
#pragma unroll
            for (int nt = 0; nt < 16; nt++)
#pragma unroll
                for (int c = 0; c < 2; c++) {
                    int col = wn * 128 + nt * 8 + cbs + c;
                    float t = acc[mt][nt][half * 2 + c] + cbp[col];
                    acc[mt][nt][half * 2 + c] = t;
                    s += t; s2 += t * t;
                }
            s += __shfl_xor_sync(0xffffffffu, s, 1);
            s += __shfl_xor_sync(0xffffffffu, s, 2);
            s2 += __shfl_xor_sync(0xffffffffu, s2, 1);
            s2 += __shfl_xor_sync(0xffffffffu, s2, 2);
            int row = wm * 32 + mt * 16 + half * 8 + r0;
            if ((lane & 3) == 0) {
                red[row * 4 + wn * 2 + 0] = s;
                red[row * 4 + wn * 2 + 1] = s2;
            }
        }
    __syncthreads();
#pragma unroll
    for (int mt = 0; mt < 2; mt++)
#pragma unroll
        for (int half = 0; half < 2; half++) {
            int row = wm * 32 + mt * 16 + half * 8 + r0;
            float s = red[row * 4 + 0] + red[row * 4 + 2];
            float s2 = red[row * 4 + 1] + red[row * 4 + 3];
            float mean = s * (1.0f / 256.0f);
            float var = s2 * (1.0f / 256.0f) - mean * mean;
            float rstd = rsqrtf(var + 1e-5f);
            float* dst = g_h2 + (size_t)(p0 + row) * 256;
#pragma unroll
            for (int nt = 0; nt < 16; nt++)
#pragma unroll
                for (int c = 0; c < 2; c++) {
                    int col = wn * 128 + nt * 8 + cbs + c;
                    float t = (acc[mt][nt][half * 2 + c] - mean) * rstd * lg[col] + lb[col];
                    dst[col] = gelu_exact(t);
                }
        }
}

// ---------------- fc: M=1024 (tile 128), N=512 (tile 128), K=4096 splitK=8 ----------------
#define FC_SMEM 147456
__global__ __launch_bounds__(256) void k_fc_mma() {
    extern __shared__ __align__(16) unsigned char sm[];
    uint32_t sb = smem_u32(sm);
    int tid = threadIdx.x, lane = tid & 31, wid = tid >> 5;
    int wm = wid & 3, wn = wid >> 2;
    int n0 = blockIdx.x * 128;
    int m0 = blockIdx.y * 128;
    int z = blockIdx.z;

#define FC_CP_B(kc, buf) do { \
    _Pragma("unroll") \
    for (int it = 0; it < 8; it++) { \
        int g = it * 256 + tid; int h = g >> 10, rem = g & 1023; \
        int n = rem >> 3, q = rem & 7; \
        cpa16(sb + 73728 + (buf) * 36864 + h * 18432 + n * 144 + q * 16, \
              (const unsigned char*)g_fcwbf + h * 4194304 + (size_t)(n0 + n) * 8192 + (z * 512 + (kc) * 64) * 2 + q * 16); \
    } CPA_COMMIT(); } while (0)

    float4 f4[8];
#define FC_LOAD_A(kc) do { \
    _Pragma("unroll") \
    for (int it = 0; it < 8; it++) { \
        int g = it * 256 + tid; int m = g >> 4, q = g & 15; \
        f4[it] = *(const float4*)(g_h2 + (size_t)(m0 + m) * 4096 + z * 512 + (kc) * 64 + q * 4); \
    } } while (0)
#define FC_STORE_A(buf) do { \
    _Pragma("unroll") \
    for (int it = 0; it < 8; it++) { \
        int g = it * 256 + tid; int m = g >> 4, q = g & 15; \
        uint2 hi, lo; cvt4((const float*)&f4[it], hi, lo); \
        *(uint2*)(sm + (buf) * 36864 + m * 144 + q * 8) = hi; \
        *(uint2*)(sm + (buf) * 36864 + 18432 + m * 144 + q * 8) = lo; \
    } } while (0)

    FC_CP_B(0, 0);
    FC_LOAD_A(0);
    FC_STORE_A(0);
    CPA_WAIT0();
    __syncthreads();

    float acc[2][8][4];
#pragma unroll
    for (int a = 0; a < 2; a++)
#pragma unroll
        for (int b = 0; b < 8; b++)
#pragma unroll
            for (int c = 0; c < 4; c++) acc[a][b][c] = 0.0f;

    for (int kc = 0; kc < 8; kc++) {
        if (kc < 7) {
            FC_CP_B(kc + 1, (kc + 1) & 1);
            FC_LOAD_A(kc + 1);
        }
        uint32_t aHi = sb + (kc & 1) * 36864 + (wm * 32 + (lane & 15)) * 144 + (lane >> 4) * 16;
        uint32_t bB = sb + 73728 + (kc & 1) * 36864 + (wn * 64 + (lane & 7)) * 144 + ((lane >> 3) & 1) * 16;
#pragma unroll
        for (int ks = 0; ks < 4; ks++) {
            uint32_t ah[2][4], al[2][4];
            ldmx4(ah[0], aHi + ks * 32);
            ldmx4(ah[1], aHi + 2304 + ks * 32);
            ldmx4(al[0], aHi + 18432 + ks * 32);
            ldmx4(al[1], aHi + 18432 + 2304 + ks * 32);
#pragma unroll
            for (int nt = 0; nt < 8; nt++) {
                uint32_t bh[2], bl[2];
                ldmx2(bh, bB + nt * 1152 + ks * 32);
                ldmx2(bl, bB + 18432 + nt * 1152 + ks * 32);
#pragma unroll
                for (int mt = 0; mt < 2; mt++) {
                    mma16816(acc[mt][nt], ah[mt], bh);
                    mma16816(acc[mt][nt], ah[mt], bl);
                    mma16816(acc[mt][nt], al[mt], bh);
                }
            }
        }
        if (kc < 7) {
            FC_STORE_A((kc + 1) & 1);
            CPA_WAIT0();
            __syncthreads();
        }
    }

    int r0 = lane >> 2, cbs = (lane & 3) * 2;
#pragma unroll
    for (int mt = 0; mt < 2; mt++)
#pragma unroll
        for (int half = 0; half < 2; half++) {
            int row = m0 + wm * 32 + mt * 16 + half * 8 + r0;
#pragma unroll
            for (int nt = 0; nt < 8; nt++)
#pragma unroll
                for (int c = 0; c < 2; c++) {
                    int col = n0 + wn * 64 + nt * 8 + cbs + c;
                    g_fcp[(size_t)z * 524288 + (size_t)row * 512 + col] = acc[mt][nt][half * 2 + c];
                }
        }
}

__global__ void k_fc_reduce(const float* __restrict__ fcb) {
    int idx = blockIdx.x * 256 + threadIdx.x;
    float s = fcb[idx & 511];
#pragma unroll
    for (int z = 0; z < 8; z++) s += g_fcp[(size_t)z * 524288 + idx];
    g_emb[idx] = s;
}

// ---------------- gating ----------------
__global__ __launch_bounds__(512) void k_gate(const float* __restrict__ wg,
                                              const int* __restrict__ topk) {
    int b = blockIdx.x;
    int d = threadIdx.x;
    float xv[16];
#pragma unroll
    for (int t = 0; t < 16; t++) xv[t] = g_emb[(size_t)(b * 16 + t) * 512 + d];

    float cs[16], sn[16];
#pragma unroll
    for (int i = 0; i < 16; i++) {
        float th = 6.283185307179586f * (float)i * (1.0f / 16.0f);
        sincosf(th, &sn[i], &cs[i]);
    }
    float amp[8];
#pragma unroll
    for (int f = 1; f <= 8; f++) {
        float re = 0.0f, im = 0.0f;
#pragma unroll
        for (int t = 0; t < 16; t++) {
            int id = (f * t) & 15;
            re += xv[t] * cs[id];
            im -= xv[t] * sn[id];
        }
        amp[f - 1] = sqrtf(re * re + im * im) * 0.25f;
    }
    __shared__ float red[16][8];
    int lane = d & 31, w = d >> 5;
#pragma unroll
    for (int f = 0; f < 8; f++) {
#pragma unroll
        for (int o = 1; o < 32; o <<= 1) amp[f] += __shfl_xor_sync(0xffffffffu, amp[f], o);
    }
    if (lane == 0)
#pragma unroll
        for (int f = 0; f < 8; f++) red[w][f] = amp[f];
    __syncthreads();
    if (d == 0) {
        float am[8];
#pragma unroll
        for (int f = 0; f < 8; f++) {
            float s = 0.0f;
            for (int ww = 0; ww < 16; ww++) s += red[ww][f];
            am[f] = s * (1.0f / 512.0f);
        }
        float lgt[6];
#pragma unroll
        for (int e = 0; e < 6; e++) {
            float s = 0.0f;
#pragma unroll
            for (int f = 0; f < 8; f++) s += am[f] * wg[f * 6 + e];
            lgt[e] = s;
        }
        int k = clamp_topk(topk);
        bool used[6] = {false, false, false, false, false, false};
        int sel[6]; float sw[6];
        for (int kk = 0; kk < k; kk++) {
            float best = -1e30f; int bi = 0;
            for (int e = 0; e < 6; e++)
                if (!used[e] && lgt[e] > best) { best = lgt[e]; bi = e; }
            used[bi] = true; sel[kk] = bi; sw[kk] = best;
        }
        float mx = sw[0], ssum = 0.0f;
        for (int kk = 0; kk < k; kk++) { sw[kk] = expf(sw[kk] - mx); ssum += sw[kk]; }
        for (int kk = 0; kk < k; kk++) {
            g_gw[b * 6 + kk] = sw[kk] / ssum;
            g_gidx[b * 6 + kk] = sel[kk];
        }
    }
}

// ---------------- experts via MMA ----------------
#define EXP_SMEM 82432
__global__ __launch_bounds__(256) void k_expert_mma(const float* __restrict__ eb,
                                                    const int* __restrict__ topk,
                                                    float* __restrict__ out) {
    extern __shared__ __align__(16) unsigned char sm[];
    uint32_t sb = smem_u32(sm);
    int tid = threadIdx.x, lane = tid & 31, wid = tid >> 5;
    int b = blockIdx.y;
    int nbase = blockIdx.x * 256;
    int k = clamp_topk(topk);

#pragma unroll
    for (int it = 0; it < 8; it++) {
        int g = it * 256 + tid;
        int m = g >> 7, q = g & 127;
        float4 v = *(const float4*)(g_emb + (size_t)(b * 16 + m) * 512 + q * 4);
        uint2 hi, lo; cvt4((const float*)&v, hi, lo);
        *(uint2*)(sm + m * 1040 + q * 8) = hi;
        *(uint2*)(sm + 16640 + m * 1040 + q * 8) = lo;
    }
    __syncthreads();

#define EXP_CP_B(e, kc, buf) do { \
    _Pragma("unroll") \
    for (int it = 0; it < 4; it++) { \
        int g = it * 256 + tid; int h = g >> 9, rem = g & 511; \
        int n = rem >> 1, part = rem & 1; \
        cpa16(sb + 33280 + (buf) * 24576 + h * 12288 + n * 48 + part * 16, \
              (const unsigned char*)g_ewbf + ((size_t)(h * 6 + (e)) * 512 + nbase + n) * 1024 + (kc) * 32 + part * 16); \
    } CPA_COMMIT(); } while (0)

    float comb[4][4];
#pragma unroll
    for (int nt = 0; nt < 4; nt++)
#pragma unroll
        for (int j = 0; j < 4; j++) comb[nt][j] = 0.0f;

    for (int ke = 0; ke < k; ke++) {
        int e = g_gidx[b * 6 + ke];
        float gv = g_gw[b * 6 + ke];

        EXP_CP_B(e, 0, 0);
        CPA_WAIT0();
        __syncthreads();

        float acc[4][4];
#pragma unroll
        for (int nt = 0; nt < 4; nt++)
#pragma unroll
            for (int j = 0; j < 4; j++) acc[nt][j] = 0.0f;

        for (int kc = 0; kc < 32; kc++) {
            if (kc < 31) EXP_CP_B(e, kc + 1, (kc + 1) & 1);
            uint32_t aOff = sb + (lane & 15) * 1040 + (lane >> 4) * 16 + kc * 32;
            uint32_t ah[4], al[4];
            ldmx4(ah, aOff);
            ldmx4(al, aOff + 16640);
            uint32_t bB = sb + 33280 + (kc & 1) * 24576 + (wid * 32 + (lane & 7)) * 48 + ((lane >> 3) & 1) * 16;
#pragma unroll
            for (int nt = 0; nt < 4; nt++) {
                uint32_t bh[2], bl[2];
                ldmx2(bh, bB + nt * 384);
                ldmx2(bl, bB + 12288 + nt * 384);
                mma16816(acc[nt], ah, bh);
                mma16816(acc[nt], ah, bl);
                mma16816(acc[nt], al, bh);
            }
            if (kc < 31) {
                CPA_WAIT0();
            }
            __syncthreads();
        }

#pragma unroll
        for (int nt = 0; nt < 4; nt++)
#pragma unroll
            for (int j = 0; j < 4; j++) {
                int col = nbase + wid * 32 + nt * 8 + (lane & 3) * 2 + (j & 1);
                float y = acc[nt][j] + eb[e * 512 + col];
                comb[nt][j] += gv * __expf(y);
            }
    }

#pragma unroll
    for (int nt = 0; nt < 4; nt++)
#pragma unroll
        for (int j = 0; j < 4; j++) {
            int col = nbase + wid * 32 + nt * 8 + (lane & 3) * 2 + (j & 1);
            int row = b * 16 + (lane >> 2) + (j >> 1) * 8;
            float c = comb[nt][j];
            if (c == 0.0f) c = LOG_EPS;
            out[(size_t)row * 512 + col] = __logf(c);
        }
}

// ---------------- launch ----------------
extern "C" void kernel_launch(void* const* d_in, const int* in_sizes, int n_in,
                              void* d_out, int out_size) {
    const float* x   = (const float*)d_in[0];
    const float* w1  = (const float*)d_in[1];
    const float* b1  = (const float*)d_in[2];
    const float* g1  = (const float*)d_in[3];
    const float* be1 = (const float*)d_in[4];
    const float* w2  = (const float*)d_in[5];
    const float* b2  = (const float*)d_in[6];
    const float* g2  = (const float*)d_in[7];
    const float* be2 = (const float*)d_in[8];
    const float* fcw = (const float*)d_in[9];
    const float* fcb = (const float*)d_in[10];
    const float* wg  = (const float*)d_in[11];
    const float* ew  = (const float*)d_in[12];
    const float* ebp = (const float*)d_in[13];
    const int* topk  = (const int*)d_in[14];
    float* out = (float*)d_out;

    cudaFuncSetAttribute(k_conv1_mma, cudaFuncAttributeMaxDynamicSharedMemorySize, C1_SMEM);
    cudaFuncSetAttribute(k_conv2_mma, cudaFuncAttributeMaxDynamicSharedMemorySize, C2_SMEM);
    cudaFuncSetAttribute(k_fc_mma, cudaFuncAttributeMaxDynamicSharedMemorySize, FC_SMEM);
    cudaFuncSetAttribute(k_expert_mma, cudaFuncAttributeMaxDynamicSharedMemorySize, EXP_SMEM);

    k_prep_w1<<<64, 256>>>(w1);
    k_prep_w2<<<1024, 256>>>(w2);
    dim3 gfcw(128, 16);
    k_prep_fcw<<<gfcw, 256>>>(fcw);
    dim3 gew(16, 16, 6);
    k_prep_ew<<<gew, 256>>>(ew);
    k_conv1_mma<<<2048, 384, C1_SMEM>>>(x, b1, g1, be1);
    k_conv2_mma<<<128, 256, C2_SMEM>>>(b2, g2, be2);
    dim3 gfc(4, 8, 8);
    k_fc_mma<<<gfc, 256, FC_SMEM>>>();
    k_fc_reduce<<<2048, 256>>>(fcb);
    k_gate<<<64, 512>>>(wg, topk);
    dim3 ge(2, 64);
    k_expert_mma<<<ge, 256, EXP_SMEM>>>(ebp, topk, out);
}

// round 11
// speedup vs baseline: 1.0594x; 1.0594x over previous
#include <cuda_runtime.h>
#include <cuda_bf16.h>
#include <math.h>
#include <stdint.h>

#define LOG_EPS 2.220446049250313e-16f

// ---------------- static scratch ----------------
__device__ __nv_bfloat16 g_h1bf[2][16777216]; // conv1 out hi/lo, [bt][qp][ij][c] (conv2 A-ready)
__device__ __nv_bfloat16 g_h2bf[2][4194304];  // conv2 out hi/lo, [bt][qp*256+c] (fc A-ready)
__device__ float g_fcp[8 * 1024 * 512];       // fc split-K partials
__device__ float g_emb[1024 * 512];
__device__ float g_gw[64 * 6];
__device__ int g_gidx[64 * 6];
__device__ __nv_bfloat16 g_w1bf[2][64][256];     // conv1 W [hi/lo][n][k]
__device__ __nv_bfloat16 g_w2bf[2][256][1024];   // conv2 W [hi/lo][n][k]
__device__ __nv_bfloat16 g_fcwbf[2][512][4096];  // fc W    [hi/lo][n][k]
__device__ __nv_bfloat16 g_ewbf[2][6][512][512]; // expert W [hi/lo][e][n][k]

// ---------------- helpers ----------------
__device__ __forceinline__ int clamp_topk(const int* topk) {
    int k = *topk;
    if (k < 1 || k > 6) {
        float fv = __int_as_float(k);
        if (fv >= 1.0f && fv <= 6.0f) k = (int)fv; else k = 2;
    }
    return k;
}
__device__ __forceinline__ float gelu_exact(float t) {
    return 0.5f * t * (1.0f + erff(t * 0.7071067811865476f));
}
__device__ __forceinline__ uint32_t smem_u32(const void* p) {
    uint32_t a;
    asm("{ .reg .u64 t; cvta.to.shared.u64 t, %1; cvt.u32.u64 %0, t; }" : "=r"(a) : "l"(p));
    return a;
}
__device__ __forceinline__ void ldmx4(uint32_t* r, uint32_t addr) {
    asm volatile("ldmatrix.sync.aligned.m8n8.x4.shared.b16 {%0,%1,%2,%3}, [%4];"
        : "=r"(r[0]), "=r"(r[1]), "=r"(r[2]), "=r"(r[3]) : "r"(addr));
}
__device__ __forceinline__ void ldmx2(uint32_t* r, uint32_t addr) {
    asm volatile("ldmatrix.sync.aligned.m8n8.x2.shared.b16 {%0,%1}, [%2];"
        : "=r"(r[0]), "=r"(r[1]) : "r"(addr));
}
__device__ __forceinline__ void mma16816(float* d, const uint32_t* a, const uint32_t* b) {
    asm volatile("mma.sync.aligned.m16n8k16.row.col.f32.bf16.bf16.f32 "
        "{%0,%1,%2,%3}, {%4,%5,%6,%7}, {%8,%9}, {%0,%1,%2,%3};"
        : "+f"(d[0]), "+f"(d[1]), "+f"(d[2]), "+f"(d[3])
        : "r"(a[0]), "r"(a[1]), "r"(a[2]), "r"(a[3]), "r"(b[0]), "r"(b[1]));
}
__device__ __forceinline__ void cvt4(const float* f, uint2& hi, uint2& lo) {
    union { __nv_bfloat16 b[4]; uint2 u; } H, L;
#pragma unroll
    for (int q = 0; q < 4; q++) {
        H.b[q] = __float2bfloat16(f[q]);
        L.b[q] = __float2bfloat16(f[q] - __bfloat162float(H.b[q]));
    }
    hi = H.u; lo = L.u;
}
__device__ __forceinline__ void cpa16(uint32_t dst, const void* src) {
    asm volatile("cp.async.cg.shared.global [%0], [%1], 16;" :: "r"(dst), "l"(src) : "memory");
}
#define CPA_COMMIT() asm volatile("cp.async.commit_group;" ::: "memory")
#define CPA_WAIT0()  asm volatile("cp.async.wait_group 0;" ::: "memory")
#define CPA_WAIT1()  asm volatile("cp.async.wait_group 1;" ::: "memory")

// write a pair of outputs as hi/lo bf16x2 into two planes
__device__ __forceinline__ void store_hilo2(__nv_bfloat16* plane_hi, __nv_bfloat16* plane_lo,
                                            size_t off, float o0, float o1) {
    union { __nv_bfloat16 b[2]; uint32_t u; } H, L;
    H.b[0] = __float2bfloat16(o0);
    H.b[1] = __float2bfloat16(o1);
    L.b[0] = __float2bfloat16(o0 - __bfloat162float(H.b[0]));
    L.b[1] = __float2bfloat16(o1 - __bfloat162float(H.b[1]));
    *(uint32_t*)&plane_hi[off] = H.u;
    *(uint32_t*)&plane_lo[off] = L.u;
}

// ---------------- weight prep ----------------
__global__ void k_prep_w1(const float* __restrict__ w) {
    int idx = blockIdx.x * 256 + threadIdx.x;
    if (idx >= 64 * 256) return;
    int o = idx >> 8, r = idx & 255;
    int c = r >> 4, i = (r >> 2) & 3, j = r & 3;
    int k = i * 64 + j * 16 + c;
    float f = w[idx];
    __nv_bfloat16 hi = __float2bfloat16(f);
    g_w1bf[0][o][k] = hi;
    g_w1bf[1][o][k] = __float2bfloat16(f - __bfloat162float(hi));
}
__global__ void k_prep_w2(const float* __restrict__ w) {
    int idx = blockIdx.x * 256 + threadIdx.x;
    if (idx >= 256 * 1024) return;
    int o = idx >> 10, k = idx & 1023;
    int cin = k & 63, ij = k >> 6;
    float f = w[o * 1024 + cin * 16 + ij];
    __nv_bfloat16 hi = __float2bfloat16(f);
    g_w2bf[0][o][k] = hi;
    g_w2bf[1][o][k] = __float2bfloat16(f - __bfloat162float(hi));
}
__global__ __launch_bounds__(256) void k_prep_fcw(const float* __restrict__ w) {
    __shared__ float ts[32][33];
    int tid = threadIdx.x;
    int kb = blockIdx.x * 32, nb = blockIdx.y * 32;
#pragma unroll
    for (int it = 0; it < 4; it++) {
        int r = it * 8 + (tid >> 5), c = tid & 31;
        ts[r][c] = w[(size_t)(kb + r) * 512 + nb + c];
    }
    __syncthreads();
    int h = tid >> 7, n = (tid >> 2) & 31, q = tid & 3;
    union { __nv_bfloat16 b[8]; uint4 u; } U;
#pragma unroll
    for (int i = 0; i < 8; i++) {
        float f = ts[q * 8 + i][n];
        __nv_bfloat16 hi = __float2bfloat16(f);
        U.b[i] = h ? __float2bfloat16(f - __bfloat162float(hi)) : hi;
    }
    *(uint4*)&g_fcwbf[h][nb + n][kb + q * 8] = U.u;
}
__global__ __launch_bounds__(256) void k_prep_ew(const float* __restrict__ w) {
    __shared__ float ts[32][33];
    int tid = threadIdx.x;
    int kb = blockIdx.x * 32, nb = blockIdx.y * 32, e = blockIdx.z;
    const float* we = w + (size_t)e * 262144;
#pragma unroll
    for (int it = 0; it < 4; it++) {
        int r = it * 8 + (tid >> 5), c = tid & 31;
        ts[r][c] = we[(size_t)(kb + r) * 512 + nb + c];
    }
    __syncthreads();
    int h = tid >> 7, n = (tid >> 2) & 31, q = tid & 3;
    union { __nv_bfloat16 b[8]; uint4 u; } U;
#pragma unroll
    for (int i = 0; i < 8; i++) {
        float f = ts[q * 8 + i][n];
        __nv_bfloat16 hi = __float2bfloat16(f);
        U.b[i] = h ? __float2bfloat16(f - __bfloat162float(hi)) : hi;
    }
    *(uint4*)&g_ewbf[h][e][nb + n][kb + q * 8] = U.u;
}

// ---------------- conv1: M=262144 (tile 256), N=64, K=256 (8 k32 chunks), cp.async pipelined ----------------
#define C1_SMEM 221184
__global__ __launch_bounds__(512, 1) void k_conv1_mma(const float* __restrict__ x,
                                                      const float* __restrict__ cbp,
                                                      const float* __restrict__ lg,
                                                      const float* __restrict__ lb) {
    extern __shared__ __align__(16) unsigned char sm[];
    uint32_t sb = smem_u32(sm);
    int tid = threadIdx.x, lane = tid & 31, wid = tid >> 5;
    int wm = wid >> 1, wn = wid & 1;
    const float* xb = x + (size_t)blockIdx.x * 65536;

#pragma unroll
    for (int it = 0; it < 8; it++) {
        int g = it * 512 + tid;
        int chunk = g >> 10, h = (g >> 9) & 1, rem = g & 511;
        int o = rem >> 3, q = rem & 7;
        uint4 v = *(const uint4*)((const unsigned char*)g_w1bf + h * 32768 + o * 512 + chunk * 128 + q * 16);
        *(uint4*)(sm + 147456 + chunk * 18432 + h * 9216 + o * 144 + q * 16) = v;
    }

#define C1_CPA(kc) do { \
    int i_ = (kc) >> 1, jp = ((kc) & 1) * 2; \
    _Pragma("unroll") \
    for (int it = 0; it < 4; it++) { \
        int g = it * 512 + tid; int m = g >> 3, q = g & 7; \
        int j = jp + (q >> 2), qc = q & 3; \
        cpa16(sb + ((kc) & 1) * 32768 + m * 128 + q * 16, \
              xb + (((m >> 4) * 4 + i_) * 64 + (m & 15) * 4 + j) * 16 + qc * 4); \
    } CPA_COMMIT(); } while (0)

#define C1_CONV(kc) do { \
    _Pragma("unroll") \
    for (int it = 0; it < 4; it++) { \
        int g = it * 512 + tid; int m = g >> 3, q = g & 7; \
        float4 v = *(const float4*)(sm + ((kc) & 1) * 32768 + m * 128 + q * 16); \
        uint2 hi, lo; cvt4((const float*)&v, hi, lo); \
        *(uint2*)(sm + 65536 + ((kc) & 1) * 40960 + m * 80 + q * 8) = hi; \
        *(uint2*)(sm + 65536 + ((kc) & 1) * 40960 + 20480 + m * 80 + q * 8) = lo; \
    } } while (0)

    C1_CPA(0);
    C1_CPA(1);
    CPA_WAIT1();
    C1_CONV(0);
    __syncthreads();

    float acc[2][4][4];
#pragma unroll
    for (int a = 0; a < 2; a++)
#pragma unroll
        for (int b = 0; b < 4; b++)
#pragma unroll
            for (int c = 0; c < 4; c++) acc[a][b][c] = 0.0f;

    for (int kc = 0; kc < 8; kc++) {
        if (kc < 6) C1_CPA(kc + 2);
        if (kc < 7) {
            if (kc < 6) CPA_WAIT1(); else CPA_WAIT0();
            C1_CONV(kc + 1);
        }
        uint32_t aHi = sb + 65536 + (kc & 1) * 40960 + (wm * 32 + (lane & 15)) * 80 + (lane >> 4) * 16;
        uint32_t bB = sb + 147456 + (kc >> 1) * 18432 + (wn * 32 + (lane & 7)) * 144 + ((lane >> 3) & 1) * 16;
#pragma unroll
        for (int ks = 0; ks < 2; ks++) {
            int ks2 = (kc & 1) * 2 + ks;
            uint32_t ah[2][4], al[2][4];
            ldmx4(ah[0], aHi + ks * 32);
            ldmx4(ah[1], aHi + 1280 + ks * 32);
            ldmx4(al[0], aHi + 20480 + ks * 32);
            ldmx4(al[1], aHi + 20480 + 1280 + ks * 32);
#pragma unroll
            for (int nt = 0; nt < 4; nt++) {
                uint32_t bh[2], bl[2];
                ldmx2(bh, bB + nt * 1152 + ks2 * 32);
                ldmx2(bl, bB + 9216 + nt * 1152 + ks2 * 32);
#pragma unroll
                for (int mt = 0; mt < 2; mt++) {
                    mma16816(acc[mt][nt], ah[mt], bh);
                    mma16816(acc[mt][nt], ah[mt], bl);
                    mma16816(acc[mt][nt], al[mt], bh);
                }
            }
        }
        __syncthreads();
    }

    // epilogue: bias + LN(64) + GELU, emit bf16 hi/lo planes in conv2's A layout [bt][qp][ij][c]
    float* red = (float*)sm;
    int r0 = lane >> 2, cbs = (lane & 3) * 2;
#pragma unroll
    for (int mt = 0; mt < 2; mt++)
#pragma unroll
        for (int half = 0; half < 2; half++) {
            float s = 0.0f, s2 = 0.0f;
#pragma unroll
            for (int nt = 0; nt < 4; nt++)
#pragma unroll
                for (int c = 0; c < 2; c++) {
                    int col = wn * 32 + nt * 8 + cbs + c;
                    float t = acc[mt][nt][half * 2 + c] + cbp[col];
                    acc[mt][nt][half * 2 + c] = t;
                    s += t; s2 += t * t;
                }
            s += __shfl_xor_sync(0xffffffffu, s, 1);
            s += __shfl_xor_sync(0xffffffffu, s, 2);
            s2 += __shfl_xor_sync(0xffffffffu, s2, 1);
            s2 += __shfl_xor_sync(0xffffffffu, s2, 2);
            int row = wm * 32 + mt * 16 + half * 8 + r0;
            if ((lane & 3) == 0) {
                red[row * 4 + wn * 2 + 0] = s;
                red[row * 4 + wn * 2 + 1] = s2;
            }
        }
    __syncthreads();
#pragma unroll
    for (int mt = 0; mt < 2; mt++)
#pragma unroll
        for (int half = 0; half < 2; half++) {
            int row = wm * 32 + mt * 16 + half * 8 + r0;
            float s = red[row * 4 + 0] + red[row * 4 + 2];
            float s2 = red[row * 4 + 1] + red[row * 4 + 3];
            float mean = s * (1.0f / 64.0f);
            float var = s2 * (1.0f / 64.0f) - mean * mean;
            float rstd = rsqrtf(var + 1e-5f);
            int ph = row >> 4, pw = row & 15;
            size_t base = (((size_t)blockIdx.x * 16 + (ph >> 2) * 4 + (pw >> 2)) * 16 +
                           ((ph & 3) * 4 + (pw & 3))) * 64;
#pragma unroll
            for (int nt = 0; nt < 4; nt++) {
                int col = wn * 32 + nt * 8 + cbs;
                float o0 = gelu_exact((acc[mt][nt][half * 2 + 0] - mean) * rstd * lg[col] + lb[col]);
                float o1 = gelu_exact((acc[mt][nt][half * 2 + 1] - mean) * rstd * lg[col + 1] + lb[col + 1]);
                store_hilo2(g_h1bf[0], g_h1bf[1], base + col, o0, o1);
            }
        }
}

// ---------------- conv2: M=16384 (tile 128), N=256, K=1024, A+B both cp.async ----------------
#define C2_SMEM 221184
__global__ __launch_bounds__(256) void k_conv2_mma(const float* __restrict__ cbp,
                                                   const float* __restrict__ lg,
                                                   const float* __restrict__ lb) {
    extern __shared__ __align__(16) unsigned char sm[];
    uint32_t sb = smem_u32(sm);
    int tid = threadIdx.x, lane = tid & 31, wid = tid >> 5;
    int wm = wid & 3, wn = wid >> 2;
    int p0 = blockIdx.x * 128;

#define C2_CP_A(kc, buf) do { \
    _Pragma("unroll") \
    for (int it = 0; it < 8; it++) { \
        int g = it * 256 + tid; int h = g >> 10, rem = g & 1023; \
        int n = rem >> 3, q = rem & 7; \
        cpa16(sb + (buf) * 36864 + h * 18432 + n * 144 + q * 16, \
              g_h1bf[0] + (size_t)h * 16777216 + ((size_t)(p0 + n) * 16 + (kc)) * 64 + q * 8); \
    } } while (0)

#define C2_CP_B(kc, buf) do { \
    _Pragma("unroll") \
    for (int it = 0; it < 16; it++) { \
        int g = it * 256 + tid; int h = g >> 11, rem = g & 2047; \
        int n = rem >> 3, q = rem & 7; \
        cpa16(sb + 73728 + (buf) * 73728 + h * 36864 + n * 144 + q * 16, \
              (const unsigned char*)g_w2bf + h * 524288 + n * 2048 + (kc) * 128 + q * 16); \
    } } while (0)

    C2_CP_A(0, 0);
    C2_CP_B(0, 0);
    CPA_COMMIT();
    CPA_WAIT0();
    __syncthreads();

    float acc[2][16][4];
#pragma unroll
    for (int a = 0; a < 2; a++)
#pragma unroll
        for (int b = 0; b < 16; b++)
#pragma unroll
            for (int c = 0; c < 4; c++) acc[a][b][c] = 0.0f;

    for (int kc = 0; kc < 16; kc++) {
        if (kc < 15) {
            C2_CP_A(kc + 1, (kc + 1) & 1);
            C2_CP_B(kc + 1, (kc + 1) & 1);
            CPA_COMMIT();
        }
        uint32_t aHi = sb + (kc & 1) * 36864 + (wm * 32 + (lane & 15)) * 144 + (lane >> 4) * 16;
        uint32_t bB = sb + 73728 + (kc & 1) * 73728 + (wn * 128 + (lane & 7)) * 144 + ((lane >> 3) & 1) * 16;
#pragma unroll
        for (int ks = 0; ks < 4; ks++) {
            uint32_t ah[2][4], al[2][4];
            ldmx4(ah[0], aHi + ks * 32);
            ldmx4(ah[1], aHi + 2304 + ks * 32);
            ldmx4(al[0], aHi + 18432 + ks * 32);
            ldmx4(al[1], aHi + 18432 + 2304 + ks * 32);
#pragma unroll
            for (int nt = 0; nt < 16; nt++) {
                uint32_t bh[2], bl[2];
                ldmx2(bh, bB + nt * 1152 + ks * 32);
                ldmx2(bl, bB + 36864 + nt * 1152 + ks * 32);
#pragma unroll
                for (int mt = 0; mt < 2; mt++) {
                    mma16816(acc[mt][nt], ah[mt], bh);
                    mma16816(acc[mt][nt], ah[mt], bl);
                    mma16816(acc[mt][nt], al[mt], bh);
                }
            }
        }
        if (kc < 15) {
            CPA_WAIT0();
            __syncthreads();
        }
    }
    __syncthreads();

    // epilogue: bias + LN(256) + GELU, emit bf16 hi/lo planes (fc A layout, linear)
    float* red = (float*)sm;
    int r0 = lane >> 2, cbs = (lane & 3) * 2;
#pragma unroll
    for (int mt = 0; mt < 2; mt++)
#pragma unroll
        for (int half = 0; half < 2; half++) {
            float s = 0.0f, s2 = 0.0f;
#pragma unroll
            for (int nt = 0; nt < 16; nt++)
#pragma unroll
                for (int c = 0; c < 2; c++) {
                    int col = wn * 128 + nt * 8 + cbs + c;
                    float t = acc[mt][nt][half * 2 + c] + cbp[col];
                    acc[mt][nt][half * 2 + c] = t;
                    s += t; s2 += t * t;
                }
            s += __shfl_xor_sync(0xffffffffu, s, 1);
            s += __shfl_xor_sync(0xffffffffu, s, 2);
            s2 += __shfl_xor_sync(0xffffffffu, s2, 1);
            s2 += __shfl_xor_sync(0xffffffffu, s2, 2);
            int row = wm * 32 + mt * 16 + half * 8 + r0;
            if ((lane & 3) == 0) {
                red[row * 4 + wn * 2 + 0] = s;
                red[row * 4 + wn * 2 + 1] = s2;
            }
        }
    __syncthreads();
#pragma unroll
    for (int mt = 0; mt < 2; mt++)
#pragma unroll
        for (int half = 0; half < 2; half++) {
            int row = wm * 32 + mt * 16 + half * 8 + r0;
            float s = red[row * 4 + 0] + red[row * 4 + 2];
            float s2 = red[row * 4 + 1] + red[row * 4 + 3];
            float mean = s * (1.0f / 256.0f);
            float var = s2 * (1.0f / 256.0f) - mean * mean;
            float rstd = rsqrtf(var + 1e-5f);
            size_t base = (size_t)(p0 + row) * 256;
#pragma unroll
            for (int nt = 0; nt < 16; nt++) {
                int col = wn * 128 + nt * 8 + cbs;
                float o0 = gelu_exact((acc[mt][nt][half * 2 + 0] - mean) * rstd * lg[col] + lb[col]);
                float o1 = gelu_exact((acc[mt][nt][half * 2 + 1] - mean) * rstd * lg[col + 1] + lb[col + 1]);
                store_hilo2(g_h2bf[0], g_h2bf[1], base + col, o0, o1);
            }
        }
}

// ---------------- fc: M=1024 (tile 128), N=512 (tile 128), K=4096 splitK=8, A+B cp.async ----------------
#define FC_SMEM 147456
__global__ __launch_bounds__(256) void k_fc_mma() {
    extern __shared__ __align__(16) unsigned char sm[];
    uint32_t sb = smem_u32(sm);
    int tid = threadIdx.x, lane = tid & 31, wid = tid >> 5;
    int wm = wid & 3, wn = wid >> 2;
    int n0 = blockIdx.x * 128;
    int m0 = blockIdx.y * 128;
    int z = blockIdx.z;

#define FC_CP_A(kc, buf) do { \
    _Pragma("unroll") \
    for (int it = 0; it < 8; it++) { \
        int g = it * 256 + tid; int h = g >> 10, rem = g & 1023; \
        int m = rem >> 3, q = rem & 7; \
        cpa16(sb + (buf) * 36864 + h * 18432 + m * 144 + q * 16, \
              g_h2bf[0] + (size_t)h * 4194304 + (size_t)(m0 + m) * 4096 + z * 512 + (kc) * 64 + q * 8); \
    } } while (0)

#define FC_CP_B(kc, buf) do { \
    _Pragma("unroll") \
    for (int it = 0; it < 8; it++) { \
        int g = it * 256 + tid; int h = g >> 10, rem = g & 1023; \
        int n = rem >> 3, q = rem & 7; \
        cpa16(sb + 73728 + (buf) * 36864 + h * 18432 + n * 144 + q * 16, \
              (const unsigned char*)g_fcwbf + h * 4194304 + (size_t)(n0 + n) * 8192 + (z * 512 + (kc) * 64) * 2 + q * 16); \
    } } while (0)

    FC_CP_A(0, 0);
    FC_CP_B(0, 0);
    CPA_COMMIT();
    CPA_WAIT0();
    __syncthreads();

    float acc[2][8][4];
#pragma unroll
    for (int a = 0; a < 2; a++)
#pragma unroll
        for (int b = 0; b < 8; b++)
#pragma unroll
            for (int c = 0; c < 4; c++) acc[a][b][c] = 0.0f;

    for (int kc = 0; kc < 8; kc++) {
        if (kc < 7) {
            FC_CP_A(kc + 1, (kc + 1) & 1);
            FC_CP_B(kc + 1, (kc + 1) & 1);
            CPA_COMMIT();
        }
        uint32_t aHi = sb + (kc & 1) * 36864 + (wm * 32 + (lane & 15)) * 144 + (lane >> 4) * 16;
        uint32_t bB = sb + 73728 + (kc & 1) * 36864 + (wn * 64 + (lane & 7)) * 144 + ((lane >> 3) & 1) * 16;
#pragma unroll
        for (int ks = 0; ks < 4; ks++) {
            uint32_t ah[2][4], al[2][4];
            ldmx4(ah[0], aHi + ks * 32);
            ldmx4(ah[1], aHi + 2304 + ks * 32);
            ldmx4(al[0], aHi + 18432 + ks * 32);
            ldmx4(al[1], aHi + 18432 + 2304 + ks * 32);
#pragma unroll
            for (int nt = 0; nt < 8; nt++) {
                uint32_t bh[2], bl[2];
                ldmx2(bh, bB + nt * 1152 + ks * 32);
                ldmx2(bl, bB + 18432 + nt * 1152 + ks * 32);
#pragma unroll
                for (int mt = 0; mt < 2; mt++) {
                    mma16816(acc[mt][nt], ah[mt], bh);
                    mma16816(acc[mt][nt], ah[mt], bl);
                    mma16816(acc[mt][nt], al[mt], bh);
                }
            }
        }
        if (kc < 7) {
            CPA_WAIT0();
            __syncthreads();
        }
    }

    int r0 = lane >> 2, cbs = (lane & 3) * 2;
#pragma unroll
    for (int mt = 0; mt < 2; mt++)
#pragma unroll
        for (int half = 0; half < 2; half++) {
            int row = m0 + wm * 32 + mt * 16 + half * 8 + r0;
#pragma unroll
            for (int nt = 0; nt < 8; nt++)
#pragma unroll
                for (int c = 0; c < 2; c++) {
                    int col = n0 + wn * 64 + nt * 8 + cbs + c;
                    g_fcp[(size_t)z * 524288 + (size_t)row * 512 + col] = acc[mt][nt][half * 2 + c];
                }
        }
}

__global__ void k_fc_reduce(const float* __restrict__ fcb) {
    int idx = blockIdx.x * 256 + threadIdx.x;
    float s = fcb[idx & 511];
#pragma unroll
    for (int z = 0; z < 8; z++) s += g_fcp[(size_t)z * 524288 + idx];
    g_emb[idx] = s;
}

// ---------------- gating ----------------
__global__ __launch_bounds__(512) void k_gate(const float* __restrict__ wg,
                                              const int* __restrict__ topk) {
    int b = blockIdx.x;
    int d = threadIdx.x;
    float xv[16];
#pragma unroll
    for (int t = 0; t < 16; t++) xv[t] = g_emb[(size_t)(b * 16 + t) * 512 + d];

    float cs[16], sn[16];
#pragma unroll
    for (int i = 0; i < 16; i++) {
        float th = 6.283185307179586f * (float)i * (1.0f / 16.0f);
        sincosf(th, &sn[i], &cs[i]);
    }
    float amp[8];
#pragma unroll
    for (int f = 1; f <= 8; f++) {
        float re = 0.0f, im = 0.0f;
#pragma unroll
        for (int t = 0; t < 16; t++) {
            int id = (f * t) & 15;
            re += xv[t] * cs[id];
            im -= xv[t] * sn[id];
        }
        amp[f - 1] = sqrtf(re * re + im * im) * 0.25f;
    }
    __shared__ float red[16][8];
    int lane = d & 31, w = d >> 5;
#pragma unroll
    for (int f = 0; f < 8; f++) {
#pragma unroll
        for (int o = 1; o < 32; o <<= 1) amp[f] += __shfl_xor_sync(0xffffffffu, amp[f], o);
    }
    if (lane == 0)
#pragma unroll
        for (int f = 0; f < 8; f++) red[w][f] = amp[f];
    __syncthreads();
    if (d == 0) {
        float am[8];
#pragma unroll
        for (int f = 0; f < 8; f++) {
            float s = 0.0f;
            for (int ww = 0; ww < 16; ww++) s += red[ww][f];
            am[f] = s * (1.0f / 512.0f);
        }
        float lgt[6];
#pragma unroll
        for (int e = 0; e < 6; e++) {
            float s = 0.0f;
#pragma unroll
            for (int f = 0; f < 8; f++) s += am[f] * wg[f * 6 + e];
            lgt[e] = s;
        }
        int k = clamp_topk(topk);
        bool used[6] = {false, false, false, false, false, false};
        int sel[6]; float sw[6];
        for (int kk = 0; kk < k; kk++) {
            float best = -1e30f; int bi = 0;
            for (int e = 0; e < 6; e++)
                if (!used[e] && lgt[e] > best) { best = lgt[e]; bi = e; }
            used[bi] = true; sel[kk] = bi; sw[kk] = best;
        }
        float mx = sw[0], ssum = 0.0f;
        for (int kk = 0; kk < k; kk++) { sw[kk] = expf(sw[kk] - mx); ssum += sw[kk]; }
        for (int kk = 0; kk < k; kk++) {
            g_gw[b * 6 + kk] = sw[kk] / ssum;
            g_gidx[b * 6 + kk] = sel[kk];
        }
    }
}

// ---------------- experts via MMA ----------------
#define EXP_SMEM 82432
__global__ __launch_bounds__(256) void k_expert_mma(const float* __restrict__ eb,
                                                    const int* __restrict__ topk,
                                                    float* __restrict__ out) {
    extern __shared__ __align__(16) unsigned char sm[];
    uint32_t sb = smem_u32(sm);
    int tid = threadIdx.x, lane = tid & 31, wid = tid >> 5;
    int b = blockIdx.y;
    int nbase = blockIdx.x * 256;
    int k = clamp_topk(topk);

#pragma unroll
    for (int it = 0; it < 8; it++) {
        int g = it * 256 + tid;
        int m = g >> 7, q = g & 127;
        float4 v = *(const float4*)(g_emb + (size_t)(b * 16 + m) * 512 + q * 4);
        uint2 hi, lo; cvt4((const float*)&v, hi, lo);
        *(uint2*)(sm + m * 1040 + q * 8) = hi;
        *(uint2*)(sm + 16640 + m * 1040 + q * 8) = lo;
    }
    __syncthreads();

#define EXP_CP_B(e, kc, buf) do { \
    _Pragma("unroll") \
    for (int it = 0; it < 4; it++) { \
        int g = it * 256 + tid; int h = g >> 9, rem = g & 511; \
        int n = rem >> 1, part = rem & 1; \
        cpa16(sb + 33280 + (buf) * 24576 + h * 12288 + n * 48 + part * 16, \
              (const unsigned char*)g_ewbf + ((size_t)(h * 6 + (e)) * 512 + nbase + n) * 1024 + (kc) * 32 + part * 16); \
    } CPA_COMMIT(); } while (0)

    float comb[4][4];
#pragma unroll
    for (int nt = 0; nt < 4; nt++)
#pragma unroll
        for (int j = 0; j < 4; j++) comb[nt][j] = 0.0f;

    for (int ke = 0; ke < k; ke++) {
        int e = g_gidx[b * 6 + ke];
        float gv = g_gw[b * 6 + ke];

        EXP_CP_B(e, 0, 0);
        CPA_WAIT0();
        __syncthreads();

        float acc[4][4];
#pragma unroll
        for (int nt = 0; nt < 4; nt++)
#pragma unroll
            for (int j = 0; j < 4; j++) acc[nt][j] = 0.0f;

        for (int kc = 0; kc < 32; kc++) {
            if (kc < 31) EXP_CP_B(e, kc + 1, (kc + 1) & 1);
            uint32_t aOff = sb + (lane & 15) * 1040 + (lane >> 4) * 16 + kc * 32;
            uint32_t ah[4], al[4];
            ldmx4(ah, aOff);
            ldmx4(al, aOff + 16640);
            uint32_t bB = sb + 33280 + (kc & 1) * 24576 + (wid * 32 + (lane & 7)) * 48 + ((lane >> 3) & 1) * 16;
#pragma unroll
            for (int nt = 0; nt < 4; nt++) {
                uint32_t bh[2], bl[2];
                ldmx2(bh, bB + nt * 384);
                ldmx2(bl, bB + 12288 + nt * 384);
                mma16816(acc[nt], ah, bh);
                mma16816(acc[nt], ah, bl);
                mma16816(acc[nt], al, bh);
            }
            if (kc < 31) {
                CPA_WAIT0();
            }
            __syncthreads();
        }

#pragma unroll
        for (int nt = 0; nt < 4; nt++)
#pragma unroll
            for (int j = 0; j < 4; j++) {
                int col = nbase + wid * 32 + nt * 8 + (lane & 3) * 2 + (j & 1);
                float y = acc[nt][j] + eb[e * 512 + col];
                comb[nt][j] += gv * __expf(y);
            }
    }

#pragma unroll
    for (int nt = 0; nt < 4; nt++)
#pragma unroll
        for (int j = 0; j < 4; j++) {
            int col = nbase + wid * 32 + nt * 8 + (lane & 3) * 2 + (j & 1);
            int row = b * 16 + (lane >> 2) + (j >> 1) * 8;
            float c = comb[nt][j];
            if (c == 0.0f) c = LOG_EPS;
            out[(size_t)row * 512 + col] = __logf(c);
        }
}

// ---------------- launch ----------------
extern "C" void kernel_launch(void* const* d_in, const int* in_sizes, int n_in,
                              void* d_out, int out_size) {
    const float* x   = (const float*)d_in[0];
    const float* w1  = (const float*)d_in[1];
    const float* b1  = (const float*)d_in[2];
    const float* g1  = (const float*)d_in[3];
    const float* be1 = (const float*)d_in[4];
    const float* w2  = (const float*)d_in[5];
    const float* b2  = (const float*)d_in[6];
    const float* g2  = (const float*)d_in[7];
    const float* be2 = (const float*)d_in[8];
    const float* fcw = (const float*)d_in[9];
    const float* fcb = (const float*)d_in[10];
    const float* wg  = (const float*)d_in[11];
    const float* ew  = (const float*)d_in[12];
    const float* ebp = (const float*)d_in[13];
    const int* topk  = (const int*)d_in[14];
    float* out = (float*)d_out;

    cudaFuncSetAttribute(k_conv1_mma, cudaFuncAttributeMaxDynamicSharedMemorySize, C1_SMEM);
    cudaFuncSetAttribute(k_conv2_mma, cudaFuncAttributeMaxDynamicSharedMemorySize, C2_SMEM);
    cudaFuncSetAttribute(k_fc_mma, cudaFuncAttributeMaxDynamicSharedMemorySize, FC_SMEM);
    cudaFuncSetAttribute(k_expert_mma, cudaFuncAttributeMaxDynamicSharedMemorySize, EXP_SMEM);

    k_prep_w1<<<64, 256>>>(w1);
    k_prep_w2<<<1024, 256>>>(w2);
    dim3 gfcw(128, 16);
    k_prep_fcw<<<gfcw, 256>>>(fcw);
    dim3 gew(16, 16, 6);
    k_prep_ew<<<gew, 256>>>(ew);
    k_conv1_mma<<<1024, 512, C1_SMEM>>>(x, b1, g1, be1);
    k_conv2_mma<<<128, 256, C2_SMEM>>>(b2, g2, be2);
    dim3 gfc(4, 8, 8);
    k_fc_mma<<<gfc, 256, FC_SMEM>>>();
    k_fc_reduce<<<2048, 256>>>(fcb);
    k_gate<<<64, 512>>>(wg, topk);
    dim3 ge(2, 64);
    k_expert_mma<<<ge, 256, EXP_SMEM>>>(ebp, topk, out);
}

// round 12
// speedup vs baseline: 1.0848x; 1.0240x over previous
#include <cuda_runtime.h>
#include <cuda_bf16.h>
#include <math.h>
#include <stdint.h>

#define LOG_EPS 2.220446049250313e-16f

// ---------------- static scratch ----------------
__device__ __nv_bfloat16 g_h1bf[2][16777216]; // conv1 out hi/lo, [bt][qp][ij][c] (conv2 A-ready)
__device__ __nv_bfloat16 g_h2bf[2][4194304];  // conv2 out hi/lo, [bt][qp*256+c] (fc A-ready)
__device__ __nv_bfloat16 g_embbf[2][524288];  // emb hi/lo (expert A-ready)
__device__ float g_fcp[8 * 1024 * 512];       // fc split-K partials
__device__ float g_gw[64 * 6];
__device__ int g_gidx[64 * 6];
__device__ __nv_bfloat16 g_w1bf[2][64][256];     // conv1 W [hi/lo][n][k]
__device__ __nv_bfloat16 g_w2bf[2][256][1024];   // conv2 W [hi/lo][n][k]
__device__ __nv_bfloat16 g_fcwbf[2][512][4096];  // fc W    [hi/lo][n][k]
__device__ __nv_bfloat16 g_ewbf[2][6][512][512]; // expert W [hi/lo][e][n][k]

// ---------------- helpers ----------------
__device__ __forceinline__ int clamp_topk(const int* topk) {
    int k = *topk;
    if (k < 1 || k > 6) {
        float fv = __int_as_float(k);
        if (fv >= 1.0f && fv <= 6.0f) k = (int)fv; else k = 2;
    }
    return k;
}
__device__ __forceinline__ float gelu_exact(float t) {
    return 0.5f * t * (1.0f + erff(t * 0.7071067811865476f));
}
__device__ __forceinline__ uint32_t smem_u32(const void* p) {
    uint32_t a;
    asm("{ .reg .u64 t; cvta.to.shared.u64 t, %1; cvt.u32.u64 %0, t; }" : "=r"(a) : "l"(p));
    return a;
}
__device__ __forceinline__ void ldmx4(uint32_t* r, uint32_t addr) {
    asm volatile("ldmatrix.sync.aligned.m8n8.x4.shared.b16 {%0,%1,%2,%3}, [%4];"
        : "=r"(r[0]), "=r"(r[1]), "=r"(r[2]), "=r"(r[3]) : "r"(addr));
}
__device__ __forceinline__ void ldmx2(uint32_t* r, uint32_t addr) {
    asm volatile("ldmatrix.sync.aligned.m8n8.x2.shared.b16 {%0,%1}, [%2];"
        : "=r"(r[0]), "=r"(r[1]) : "r"(addr));
}
__device__ __forceinline__ void mma16816(float* d, const uint32_t* a, const uint32_t* b) {
    asm volatile("mma.sync.aligned.m16n8k16.row.col.f32.bf16.bf16.f32 "
        "{%0,%1,%2,%3}, {%4,%5,%6,%7}, {%8,%9}, {%0,%1,%2,%3};"
        : "+f"(d[0]), "+f"(d[1]), "+f"(d[2]), "+f"(d[3])
        : "r"(a[0]), "r"(a[1]), "r"(a[2]), "r"(a[3]), "r"(b[0]), "r"(b[1]));
}
__device__ __forceinline__ void cvt4(const float* f, uint2& hi, uint2& lo) {
    union { __nv_bfloat16 b[4]; uint2 u; } H, L;
#pragma unroll
    for (int q = 0; q < 4; q++) {
        H.b[q] = __float2bfloat16(f[q]);
        L.b[q] = __float2bfloat16(f[q] - __bfloat162float(H.b[q]));
    }
    hi = H.u; lo = L.u;
}
__device__ __forceinline__ void cpa16(uint32_t dst, const void* src) {
    asm volatile("cp.async.cg.shared.global [%0], [%1], 16;" :: "r"(dst), "l"(src) : "memory");
}
#define CPA_COMMIT() asm volatile("cp.async.commit_group;" ::: "memory")
#define CPA_WAIT0()  asm volatile("cp.async.wait_group 0;" ::: "memory")
#define CPA_WAIT1()  asm volatile("cp.async.wait_group 1;" ::: "memory")

__device__ __forceinline__ void store_hilo2(__nv_bfloat16* plane_hi, __nv_bfloat16* plane_lo,
                                            size_t off, float o0, float o1) {
    union { __nv_bfloat16 b[2]; uint32_t u; } H, L;
    H.b[0] = __float2bfloat16(o0);
    H.b[1] = __float2bfloat16(o1);
    L.b[0] = __float2bfloat16(o0 - __bfloat162float(H.b[0]));
    L.b[1] = __float2bfloat16(o1 - __bfloat162float(H.b[1]));
    *(uint32_t*)&plane_hi[off] = H.u;
    *(uint32_t*)&plane_lo[off] = L.u;
}

// ---------------- weight prep ----------------
__global__ void k_prep_w1(const float* __restrict__ w) {
    int idx = blockIdx.x * 256 + threadIdx.x;
    if (idx >= 64 * 256) return;
    int o = idx >> 8, r = idx & 255;
    int c = r >> 4, i = (r >> 2) & 3, j = r & 3;
    int k = i * 64 + j * 16 + c;
    float f = w[idx];
    __nv_bfloat16 hi = __float2bfloat16(f);
    g_w1bf[0][o][k] = hi;
    g_w1bf[1][o][k] = __float2bfloat16(f - __bfloat162float(hi));
}
__global__ void k_prep_w2(const float* __restrict__ w) {
    int idx = blockIdx.x * 256 + threadIdx.x;
    if (idx >= 256 * 1024) return;
    int o = idx >> 10, k = idx & 1023;
    int cin = k & 63, ij = k >> 6;
    float f = w[o * 1024 + cin * 16 + ij];
    __nv_bfloat16 hi = __float2bfloat16(f);
    g_w2bf[0][o][k] = hi;
    g_w2bf[1][o][k] = __float2bfloat16(f - __bfloat162float(hi));
}
__global__ __launch_bounds__(256) void k_prep_fcw(const float* __restrict__ w) {
    __shared__ float ts[32][33];
    int tid = threadIdx.x;
    int kb = blockIdx.x * 32, nb = blockIdx.y * 32;
#pragma unroll
    for (int it = 0; it < 4; it++) {
        int r = it * 8 + (tid >> 5), c = tid & 31;
        ts[r][c] = w[(size_t)(kb + r) * 512 + nb + c];
    }
    __syncthreads();
    int h = tid >> 7, n = (tid >> 2) & 31, q = tid & 3;
    union { __nv_bfloat16 b[8]; uint4 u; } U;
#pragma unroll
    for (int i = 0; i < 8; i++) {
        float f = ts[q * 8 + i][n];
        __nv_bfloat16 hi = __float2bfloat16(f);
        U.b[i] = h ? __float2bfloat16(f - __bfloat162float(hi)) : hi;
    }
    *(uint4*)&g_fcwbf[h][nb + n][kb + q * 8] = U.u;
}
__global__ __launch_bounds__(256) void k_prep_ew(const float* __restrict__ w) {
    __shared__ float ts[32][33];
    int tid = threadIdx.x;
    int kb = blockIdx.x * 32, nb = blockIdx.y * 32, e = blockIdx.z;
    const float* we = w + (size_t)e * 262144;
#pragma unroll
    for (int it = 0; it < 4; it++) {
        int r = it * 8 + (tid >> 5), c = tid & 31;
        ts[r][c] = we[(size_t)(kb + r) * 512 + nb + c];
    }
    __syncthreads();
    int h = tid >> 7, n = (tid >> 2) & 31, q = tid & 3;
    union { __nv_bfloat16 b[8]; uint4 u; } U;
#pragma unroll
    for (int i = 0; i < 8; i++) {
        float f = ts[q * 8 + i][n];
        __nv_bfloat16 hi = __float2bfloat16(f);
        U.b[i] = h ? __float2bfloat16(f - __bfloat162float(hi)) : hi;
    }
    *(uint4*)&g_ewbf[h][e][nb + n][kb + q * 8] = U.u;
}

// ---------------- conv1: M=262144 (tile 256), N=64, K=256 (8 k32 chunks), cp.async pipelined ----------------
#define C1_SMEM 221184
__global__ __launch_bounds__(512, 1) void k_conv1_mma(const float* __restrict__ x,
                                                      const float* __restrict__ cbp,
                                                      const float* __restrict__ lg,
                                                      const float* __restrict__ lb) {
    extern __shared__ __align__(16) unsigned char sm[];
    uint32_t sb = smem_u32(sm);
    int tid = threadIdx.x, lane = tid & 31, wid = tid >> 5;
    int wm = wid >> 1, wn = wid & 1;
    const float* xb = x + (size_t)blockIdx.x * 65536;

#pragma unroll
    for (int it = 0; it < 8; it++) {
        int g = it * 512 + tid;
        int chunk = g >> 10, h = (g >> 9) & 1, rem = g & 511;
        int o = rem >> 3, q = rem & 7;
        uint4 v = *(const uint4*)((const unsigned char*)g_w1bf + h * 32768 + o * 512 + chunk * 128 + q * 16);
        *(uint4*)(sm + 147456 + chunk * 18432 + h * 9216 + o * 144 + q * 16) = v;
    }

#define C1_CPA(kc) do { \
    int i_ = (kc) >> 1, jp = ((kc) & 1) * 2; \
    _Pragma("unroll") \
    for (int it = 0; it < 4; it++) { \
        int g = it * 512 + tid; int m = g >> 3, q = g & 7; \
        int j = jp + (q >> 2), qc = q & 3; \
        cpa16(sb + ((kc) & 1) * 32768 + m * 128 + q * 16, \
              xb + (((m >> 4) * 4 + i_) * 64 + (m & 15) * 4 + j) * 16 + qc * 4); \
    } CPA_COMMIT(); } while (0)

#define C1_CONV(kc) do { \
    _Pragma("unroll") \
    for (int it = 0; it < 4; it++) { \
        int g = it * 512 + tid; int m = g >> 3, q = g & 7; \
        float4 v = *(const float4*)(sm + ((kc) & 1) * 32768 + m * 128 + q * 16); \
        uint2 hi, lo; cvt4((const float*)&v, hi, lo); \
        *(uint2*)(sm + 65536 + ((kc) & 1) * 40960 + m * 80 + q * 8) = hi; \
        *(uint2*)(sm + 65536 + ((kc) & 1) * 40960 + 20480 + m * 80 + q * 8) = lo; \
    } } while (0)

    C1_CPA(0);
    C1_CPA(1);
    CPA_WAIT1();
    C1_CONV(0);
    __syncthreads();

    float acc[2][4][4];
#pragma unroll
    for (int a = 0; a < 2; a++)
#pragma unroll
        for (int b = 0; b < 4; b++)
#pragma unroll
            for (int c = 0; c < 4; c++) acc[a][b][c] = 0.0f;

    for (int kc = 0; kc < 8; kc++) {
        if (kc < 6) C1_CPA(kc + 2);
        if (kc < 7) {
            if (kc < 6) CPA_WAIT1(); else CPA_WAIT0();
            C1_CONV(kc + 1);
        }
        uint32_t aHi = sb + 65536 + (kc & 1) * 40960 + (wm * 32 + (lane & 15)) * 80 + (lane >> 4) * 16;
        uint32_t bB = sb + 147456 + (kc >> 1) * 18432 + (wn * 32 + (lane & 7)) * 144 + ((lane >> 3) & 1) * 16;
#pragma unroll
        for (int ks = 0; ks < 2; ks++) {
            int ks2 = (kc & 1) * 2 + ks;
            uint32_t ah[2][4], al[2][4];
            ldmx4(ah[0], aHi + ks * 32);
            ldmx4(ah[1], aHi + 1280 + ks * 32);
            ldmx4(al[0], aHi + 20480 + ks * 32);
            ldmx4(al[1], aHi + 20480 + 1280 + ks * 32);
#pragma unroll
            for (int nt = 0; nt < 4; nt++) {
                uint32_t bh[2], bl[2];
                ldmx2(bh, bB + nt * 1152 + ks2 * 32);
                ldmx2(bl, bB + 9216 + nt * 1152 + ks2 * 32);
#pragma unroll
                for (int mt = 0; mt < 2; mt++) {
                    mma16816(acc[mt][nt], ah[mt], bh);
                    mma16816(acc[mt][nt], ah[mt], bl);
                    mma16816(acc[mt][nt], al[mt], bh);
                }
            }
        }
        __syncthreads();
    }

    float* red = (float*)sm;
    int r0 = lane >> 2, cbs = (lane & 3) * 2;
#pragma unroll
    for (int mt = 0; mt < 2; mt++)
#pragma unroll
        for (int half = 0; half < 2; half++) {
            float s = 0.0f, s2 = 0.0f;
#pragma unroll
            for (int nt = 0; nt < 4; nt++)
#pragma unroll
                for (int c = 0; c < 2; c++) {
                    int col = wn * 32 + nt * 8 + cbs + c;
                    float t = acc[mt][nt][half * 2 + c] + cbp[col];
                    acc[mt][nt][half * 2 + c] = t;
                    s += t; s2 += t * t;
                }
            s += __shfl_xor_sync(0xffffffffu, s, 1);
            s += __shfl_xor_sync(0xffffffffu, s, 2);
            s2 += __shfl_xor_sync(0xffffffffu, s2, 1);
            s2 += __shfl_xor_sync(0xffffffffu, s2, 2);
            int row = wm * 32 + mt * 16 + half * 8 + r0;
            if ((lane & 3) == 0) {
                red[row * 4 + wn * 2 + 0] = s;
                red[row * 4 + wn * 2 + 1] = s2;
            }
        }
    __syncthreads();
#pragma unroll
    for (int mt = 0; mt < 2; mt++)
#pragma unroll
        for (int half = 0; half < 2; half++) {
            int row = wm * 32 + mt * 16 + half * 8 + r0;
            float s = red[row * 4 + 0] + red[row * 4 + 2];
            float s2 = red[row * 4 + 1] + red[row * 4 + 3];
            float mean = s * (1.0f / 64.0f);
            float var = s2 * (1.0f / 64.0f) - mean * mean;
            float rstd = rsqrtf(var + 1e-5f);
            int ph = row >> 4, pw = row & 15;
            size_t base = (((size_t)blockIdx.x * 16 + (ph >> 2) * 4 + (pw >> 2)) * 16 +
                           ((ph & 3) * 4 + (pw & 3))) * 64;
#pragma unroll
            for (int nt = 0; nt < 4; nt++) {
                int col = wn * 32 + nt * 8 + cbs;
                float o0 = gelu_exact((acc[mt][nt][half * 2 + 0] - mean) * rstd * lg[col] + lb[col]);
                float o1 = gelu_exact((acc[mt][nt][half * 2 + 1] - mean) * rstd * lg[col + 1] + lb[col + 1]);
                store_hilo2(g_h1bf[0], g_h1bf[1], base + col, o0, o1);
            }
        }
}

// ---------------- conv2: M=16384 (tile 128), N=256, K=1024, A+B both cp.async ----------------
#define C2_SMEM 221184
__global__ __launch_bounds__(256) void k_conv2_mma(const float* __restrict__ cbp,
                                                   const float* __restrict__ lg,
                                                   const float* __restrict__ lb) {
    extern __shared__ __align__(16) unsigned char sm[];
    uint32_t sb = smem_u32(sm);
    int tid = threadIdx.x, lane = tid & 31, wid = tid >> 5;
    int wm = wid & 3, wn = wid >> 2;
    int p0 = blockIdx.x * 128;

#define C2_CP_A(kc, buf) do { \
    _Pragma("unroll") \
    for (int it = 0; it < 8; it++) { \
        int g = it * 256 + tid; int h = g >> 10, rem = g & 1023; \
        int n = rem >> 3, q = rem & 7; \
        cpa16(sb + (buf) * 36864 + h * 18432 + n * 144 + q * 16, \
              g_h1bf[0] + (size_t)h * 16777216 + ((size_t)(p0 + n) * 16 + (kc)) * 64 + q * 8); \
    } } while (0)

#define C2_CP_B(kc, buf) do { \
    _Pragma("unroll") \
    for (int it = 0; it < 16; it++) { \
        int g = it * 256 + tid; int h = g >> 11, rem = g & 2047; \
        int n = rem >> 3, q = rem & 7; \
        cpa16(sb + 73728 + (buf) * 73728 + h * 36864 + n * 144 + q * 16, \
              (const unsigned char*)g_w2bf + h * 524288 + n * 2048 + (kc) * 128 + q * 16); \
    } } while (0)

    C2_CP_A(0, 0);
    C2_CP_B(0, 0);
    CPA_COMMIT();
    CPA_WAIT0();
    __syncthreads();

    float acc[2][16][4];
#pragma unroll
    for (int a = 0; a < 2; a++)
#pragma unroll
        for (int b = 0; b < 16; b++)
#pragma unroll
            for (int c = 0; c < 4; c++) acc[a][b][c] = 0.0f;

    for (int kc = 0; kc < 16; kc++) {
        if (kc < 15) {
            C2_CP_A(kc + 1, (kc + 1) & 1);
            C2_CP_B(kc + 1, (kc + 1) & 1);
            CPA_COMMIT();
        }
        uint32_t aHi = sb + (kc & 1) * 36864 + (wm * 32 + (lane & 15)) * 144 + (lane >> 4) * 16;
        uint32_t bB = sb + 73728 + (kc & 1) * 73728 + (wn * 128 + (lane & 7)) * 144 + ((lane >> 3) & 1) * 16;
#pragma unroll
        for (int ks = 0; ks < 4; ks++) {
            uint32_t ah[2][4], al[2][4];
            ldmx4(ah[0], aHi + ks * 32);
            ldmx4(ah[1], aHi + 2304 + ks * 32);
            ldmx4(al[0], aHi + 18432 + ks * 32);
            ldmx4(al[1], aHi + 18432 + 2304 + ks * 32);
#pragma unroll
            for (int nt = 0; nt < 16; nt++) {
                uint32_t bh[2], bl[2];
                ldmx2(bh, bB + nt * 1152 + ks * 32);
                ldmx2(bl, bB + 36864 + nt * 1152 + ks * 32);
#pragma unroll
                for (int mt = 0; mt < 2; mt++) {
                    mma16816(acc[mt][nt], ah[mt], bh);
                    mma16816(acc[mt][nt], ah[mt], bl);
                    mma16816(acc[mt][nt], al[mt], bh);
                }
            }
        }
        if (kc < 15) {
            CPA_WAIT0();
            __syncthreads();
        }
    }
    __syncthreads();

    float* red = (float*)sm;
    int r0 = lane >> 2, cbs = (lane & 3) * 2;
#pragma unroll
    for (int mt = 0; mt < 2; mt++)
#pragma unroll
        for (int half = 0; half < 2; half++) {
            float s = 0.0f, s2 = 0.0f;
#pragma unroll
            for (int nt = 0; nt < 16; nt++)
#pragma unroll
                for (int c = 0; c < 2; c++) {
                    int col = wn * 128 + nt * 8 + cbs + c;
                    float t = acc[mt][nt][half * 2 + c] + cbp[col];
                    acc[mt][nt][half * 2 + c] = t;
                    s += t; s2 += t * t;
                }
            s += __shfl_xor_sync(0xffffffffu, s, 1);
            s += __shfl_xor_sync(0xffffffffu, s, 2);
            s2 += __shfl_xor_sync(0xffffffffu, s2, 1);
            s2 += __shfl_xor_sync(0xffffffffu, s2, 2);
            int row = wm * 32 + mt * 16 + half * 8 + r0;
            if ((lane & 3) == 0) {
                red[row * 4 + wn * 2 + 0] = s;
                red[row * 4 + wn * 2 + 1] = s2;
            }
        }
    __syncthreads();
#pragma unroll
    for (int mt = 0; mt < 2; mt++)
#pragma unroll
        for (int half = 0; half < 2; half++) {
            int row = wm * 32 + mt * 16 + half * 8 + r0;
            float s = red[row * 4 + 0] + red[row * 4 + 2];
            float s2 = red[row * 4 + 1] + red[row * 4 + 3];
            float mean = s * (1.0f / 256.0f);
            float var = s2 * (1.0f / 256.0f) - mean * mean;
            float rstd = rsqrtf(var + 1e-5f);
            size_t base = (size_t)(p0 + row) * 256;
#pragma unroll
            for (int nt = 0; nt < 16; nt++) {
                int col = wn * 128 + nt * 8 + cbs;
                float o0 = gelu_exact((acc[mt][nt][half * 2 + 0] - mean) * rstd * lg[col] + lb[col]);
                float o1 = gelu_exact((acc[mt][nt][half * 2 + 1] - mean) * rstd * lg[col + 1] + lb[col + 1]);
                store_hilo2(g_h2bf[0], g_h2bf[1], base + col, o0, o1);
            }
        }
}

// ---------------- fc: M=1024 (tile 128), N=512 (tile 128), K=4096 splitK=8, A+B cp.async ----------------
#define FC_SMEM 147456
__global__ __launch_bounds__(256) void k_fc_mma() {
    extern __shared__ __align__(16) unsigned char sm[];
    uint32_t sb = smem_u32(sm);
    int tid = threadIdx.x, lane = tid & 31, wid = tid >> 5;
    int wm = wid & 3, wn = wid >> 2;
    int n0 = blockIdx.x * 128;
    int m0 = blockIdx.y * 128;
    int z = blockIdx.z;

#define FC_CP_A(kc, buf) do { \
    _Pragma("unroll") \
    for (int it = 0; it < 8; it++) { \
        int g = it * 256 + tid; int h = g >> 10, rem = g & 1023; \
        int m = rem >> 3, q = rem & 7; \
        cpa16(sb + (buf) * 36864 + h * 18432 + m * 144 + q * 16, \
              g_h2bf[0] + (size_t)h * 4194304 + (size_t)(m0 + m) * 4096 + z * 512 + (kc) * 64 + q * 8); \
    } } while (0)

#define FC_CP_B(kc, buf) do { \
    _Pragma("unroll") \
    for (int it = 0; it < 8; it++) { \
        int g = it * 256 + tid; int h = g >> 10, rem = g & 1023; \
        int n = rem >> 3, q = rem & 7; \
        cpa16(sb + 73728 + (buf) * 36864 + h * 18432 + n * 144 + q * 16, \
              (const unsigned char*)g_fcwbf + h * 4194304 + (size_t)(n0 + n) * 8192 + (z * 512 + (kc) * 64) * 2 + q * 16); \
    } } while (0)

    FC_CP_A(0, 0);
    FC_CP_B(0, 0);
    CPA_COMMIT();
    CPA_WAIT0();
    __syncthreads();

    float acc[2][8][4];
#pragma unroll
    for (int a = 0; a < 2; a++)
#pragma unroll
        for (int b = 0; b < 8; b++)
#pragma unroll
            for (int c = 0; c < 4; c++) acc[a][b][c] = 0.0f;

    for (int kc = 0; kc < 8; kc++) {
        if (kc < 7) {
            FC_CP_A(kc + 1, (kc + 1) & 1);
            FC_CP_B(kc + 1, (kc + 1) & 1);
            CPA_COMMIT();
        }
        uint32_t aHi = sb + (kc & 1) * 36864 + (wm * 32 + (lane & 15)) * 144 + (lane >> 4) * 16;
        uint32_t bB = sb + 73728 + (kc & 1) * 36864 + (wn * 64 + (lane & 7)) * 144 + ((lane >> 3) & 1) * 16;
#pragma unroll
        for (int ks = 0; ks < 4; ks++) {
            uint32_t ah[2][4], al[2][4];
            ldmx4(ah[0], aHi + ks * 32);
            ldmx4(ah[1], aHi + 2304 + ks * 32);
            ldmx4(al[0], aHi + 18432 + ks * 32);
            ldmx4(al[1], aHi + 18432 + 2304 + ks * 32);
#pragma unroll
            for (int nt = 0; nt < 8; nt++) {
                uint32_t bh[2], bl[2];
                ldmx2(bh, bB + nt * 1152 + ks * 32);
                ldmx2(bl, bB + 18432 + nt * 1152 + ks * 32);
#pragma unroll
                for (int mt = 0; mt < 2; mt++) {
                    mma16816(acc[mt][nt], ah[mt], bh);
                    mma16816(acc[mt][nt], ah[mt], bl);
                    mma16816(acc[mt][nt], al[mt], bh);
                }
            }
        }
        if (kc < 7) {
            CPA_WAIT0();
            __syncthreads();
        }
    }

    int r0 = lane >> 2, cbs = (lane & 3) * 2;
#pragma unroll
    for (int mt = 0; mt < 2; mt++)
#pragma unroll
        for (int half = 0; half < 2; half++) {
            int row = m0 + wm * 32 + mt * 16 + half * 8 + r0;
#pragma unroll
            for (int nt = 0; nt < 8; nt++)
#pragma unroll
                for (int c = 0; c < 2; c++) {
                    int col = n0 + wn * 64 + nt * 8 + cbs + c;
                    g_fcp[(size_t)z * 524288 + (size_t)row * 512 + col] = acc[mt][nt][half * 2 + c];
                }
        }
}

// ---------------- gating (fused split-K reduce + bf16 emb emit + DFT top-k) ----------------
__global__ __launch_bounds__(512) void k_gate(const float* __restrict__ fcb,
                                              const float* __restrict__ wg,
                                              const int* __restrict__ topk) {
    int b = blockIdx.x;
    int d = threadIdx.x;
    float bias = fcb[d];
    float xv[16];
#pragma unroll
    for (int t = 0; t < 16; t++) {
        size_t off = (size_t)(b * 16 + t) * 512 + d;
        float s = bias;
#pragma unroll
        for (int z = 0; z < 8; z++) s += g_fcp[(size_t)z * 524288 + off];
        xv[t] = s;
        __nv_bfloat16 hi = __float2bfloat16(s);
        g_embbf[0][off] = hi;
        g_embbf[1][off] = __float2bfloat16(s - __bfloat162float(hi));
    }

    float cs[16], sn[16];
#pragma unroll
    for (int i = 0; i < 16; i++) {
        float th = 6.283185307179586f * (float)i * (1.0f / 16.0f);
        sincosf(th, &sn[i], &cs[i]);
    }
    float amp[8];
#pragma unroll
    for (int f = 1; f <= 8; f++) {
        float re = 0.0f, im = 0.0f;
#pragma unroll
        for (int t = 0; t < 16; t++) {
            int id = (f * t) & 15;
            re += xv[t] * cs[id];
            im -= xv[t] * sn[id];
        }
        amp[f - 1] = sqrtf(re * re + im * im) * 0.25f;
    }
    __shared__ float red[16][8];
    int lane = d & 31, w = d >> 5;
#pragma unroll
    for (int f = 0; f < 8; f++) {
#pragma unroll
        for (int o = 1; o < 32; o <<= 1) amp[f] += __shfl_xor_sync(0xffffffffu, amp[f], o);
    }
    if (lane == 0)
#pragma unroll
        for (int f = 0; f < 8; f++) red[w][f] = amp[f];
    __syncthreads();
    if (d == 0) {
        float am[8];
#pragma unroll
        for (int f = 0; f < 8; f++) {
            float s = 0.0f;
            for (int ww = 0; ww < 16; ww++) s += red[ww][f];
            am[f] = s * (1.0f / 512.0f);
        }
        float lgt[6];
#pragma unroll
        for (int e = 0; e < 6; e++) {
            float s = 0.0f;
#pragma unroll
            for (int f = 0; f < 8; f++) s += am[f] * wg[f * 6 + e];
            lgt[e] = s;
        }
        int k = clamp_topk(topk);
        bool used[6] = {false, false, false, false, false, false};
        int sel[6]; float sw[6];
        for (int kk = 0; kk < k; kk++) {
            float best = -1e30f; int bi = 0;
            for (int e = 0; e < 6; e++)
                if (!used[e] && lgt[e] > best) { best = lgt[e]; bi = e; }
            used[bi] = true; sel[kk] = bi; sw[kk] = best;
        }
        float mx = sw[0], ssum = 0.0f;
        for (int kk = 0; kk < k; kk++) { sw[kk] = expf(sw[kk] - mx); ssum += sw[kk]; }
        for (int kk = 0; kk < k; kk++) {
            g_gw[b * 6 + kk] = sw[kk] / ssum;
            g_gidx[b * 6 + kk] = sel[kk];
        }
    }
}

// ---------------- experts via MMA: k32 chunks (16 iters), A via cp.async from g_embbf ----------------
// smem: A_hi [0,16640) 16 rows x 1040, A_lo [16640,33280),
//       B buf{0,1} at 33280 + buf*40960: per buf hi 256x80=20480, lo +20480
#define EXP_SMEM 115200
__global__ __launch_bounds__(256) void k_expert_mma(const float* __restrict__ eb,
                                                    const int* __restrict__ topk,
                                                    float* __restrict__ out) {
    extern __shared__ __align__(16) unsigned char sm[];
    uint32_t sb = smem_u32(sm);
    int tid = threadIdx.x, lane = tid & 31, wid = tid >> 5;
    int b = blockIdx.y;
    int nbase = blockIdx.x * 256;
    int k = clamp_topk(topk);

    // A: cp.async hi/lo emb rows (16 x 512 bf16 each plane)
#pragma unroll
    for (int it = 0; it < 8; it++) {
        int g = it * 256 + tid;
        int h = g >> 10, rem = g & 1023;
        int m = rem >> 6, q = rem & 63;
        cpa16(sb + h * 16640 + m * 1040 + q * 16,
              g_embbf[h] + (size_t)(b * 16 + m) * 512 + q * 8);
    }
    CPA_COMMIT();

// B k32 chunk: 2 halves x 256 rows x 4 x 16B = 2048 cpa16 -> 8 iters
#define EXP_CP_B(e, kc, buf) do { \
    _Pragma("unroll") \
    for (int it = 0; it < 8; it++) { \
        int g = it * 256 + tid; int h = g >> 10, rem = g & 1023; \
        int n = rem >> 2, part = rem & 3; \
        cpa16(sb + 33280 + (buf) * 40960 + h * 20480 + n * 80 + part * 16, \
              (const unsigned char*)g_ewbf + ((size_t)(h * 6 + (e)) * 512 + nbase + n) * 1024 + (kc) * 64 + part * 16); \
    } CPA_COMMIT(); } while (0)

    float comb[4][4];
#pragma unroll
    for (int nt = 0; nt < 4; nt++)
#pragma unroll
        for (int j = 0; j < 4; j++) comb[nt][j] = 0.0f;

    for (int ke = 0; ke < k; ke++) {
        int e = g_gidx[b * 6 + ke];
        float gv = g_gw[b * 6 + ke];

        EXP_CP_B(e, 0, 0);
        CPA_WAIT0();
        __syncthreads();

        float acc[4][4];
#pragma unroll
        for (int nt = 0; nt < 4; nt++)
#pragma unroll
            for (int j = 0; j < 4; j++) acc[nt][j] = 0.0f;

        for (int kc = 0; kc < 16; kc++) {
            if (kc < 15) EXP_CP_B(e, kc + 1, (kc + 1) & 1);
#pragma unroll
            for (int ks = 0; ks < 2; ks++) {
                uint32_t aOff = sb + (lane & 15) * 1040 + (lane >> 4) * 16 + kc * 64 + ks * 32;
                uint32_t ah[4], al[4];
                ldmx4(ah, aOff);
                ldmx4(al, aOff + 16640);
                uint32_t bB = sb + 33280 + (kc & 1) * 40960 + (wid * 32 + (lane & 7)) * 80 +
                              ((lane >> 3) & 1) * 16 + ks * 32;
#pragma unroll
                for (int nt = 0; nt < 4; nt++) {
                    uint32_t bh[2], bl[2];
                    ldmx2(bh, bB + nt * 640);
                    ldmx2(bl, bB + 20480 + nt * 640);
                    mma16816(acc[nt], ah, bh);
                    mma16816(acc[nt], ah, bl);
                    mma16816(acc[nt], al, bh);
                }
            }
            if (kc < 15) {
                CPA_WAIT0();
                __syncthreads();
            }
        }

#pragma unroll
        for (int nt = 0; nt < 4; nt++)
#pragma unroll
            for (int j = 0; j < 4; j++) {
                int col = nbase + wid * 32 + nt * 8 + (lane & 3) * 2 + (j & 1);
                float y = acc[nt][j] + eb[e * 512 + col];
                comb[nt][j] += gv * __expf(y);
            }
    }

#pragma unroll
    for (int nt = 0; nt < 4; nt++)
#pragma unroll
        for (int j = 0; j < 4; j++) {
            int col = nbase + wid * 32 + nt * 8 + (lane & 3) * 2 + (j & 1);
            int row = b * 16 + (lane >> 2) + (j >> 1) * 8;
            float c = comb[nt][j];
            if (c == 0.0f) c = LOG_EPS;
            out[(size_t)row * 512 + col] = __logf(c);
        }
}

// ---------------- launch ----------------
extern "C" void kernel_launch(void* const* d_in, const int* in_sizes, int n_in,
                              void* d_out, int out_size) {
    const float* x   = (const float*)d_in[0];
    const float* w1  = (const float*)d_in[1];
    const float* b1  = (const float*)d_in[2];
    const float* g1  = (const float*)d_in[3];
    const float* be1 = (const float*)d_in[4];
    const float* w2  = (const float*)d_in[5];
    const float* b2  = (const float*)d_in[6];
    const float* g2  = (const float*)d_in[7];
    const float* be2 = (const float*)d_in[8];
    const float* fcw = (const float*)d_in[9];
    const float* fcb = (const float*)d_in[10];
    const float* wg  = (const float*)d_in[11];
    const float* ew  = (const float*)d_in[12];
    const float* ebp = (const float*)d_in[13];
    const int* topk  = (const int*)d_in[14];
    float* out = (float*)d_out;

    cudaFuncSetAttribute(k_conv1_mma, cudaFuncAttributeMaxDynamicSharedMemorySize, C1_SMEM);
    cudaFuncSetAttribute(k_conv2_mma, cudaFuncAttributeMaxDynamicSharedMemorySize, C2_SMEM);
    cudaFuncSetAttribute(k_fc_mma, cudaFuncAttributeMaxDynamicSharedMemorySize, FC_SMEM);
    cudaFuncSetAttribute(k_expert_mma, cudaFuncAttributeMaxDynamicSharedMemorySize, EXP_SMEM);

    k_prep_w1<<<64, 256>>>(w1);
    k_prep_w2<<<1024, 256>>>(w2);
    dim3 gfcw(128, 16);
    k_prep_fcw<<<gfcw, 256>>>(fcw);
    dim3 gew(16, 16, 6);
    k_prep_ew<<<gew, 256>>>(ew);
    k_conv1_mma<<<1024, 512, C1_SMEM>>>(x, b1, g1, be1);
    k_conv2_mma<<<128, 256, C2_SMEM>>>(b2, g2, be2);
    dim3 gfc(4, 8, 8);
    k_fc_mma<<<gfc, 256, FC_SMEM>>>();
    k_gate<<<64, 512>>>(fcb, wg, topk);
    dim3 ge(2, 64);
    k_expert_mma<<<ge, 256, EXP_SMEM>>>(ebp, topk, out);
}

// round 13
// speedup vs baseline: 1.0991x; 1.0132x over previous
#include <cuda_runtime.h>
#include <cuda_bf16.h>
#include <math.h>
#include <stdint.h>

#define LOG_EPS 2.220446049250313e-16f

// ---------------- static scratch ----------------
__device__ __nv_bfloat16 g_h1bf[2][16777216]; // conv1 out hi/lo, [bt][qp][ij][c] (conv2 A-ready)
__device__ __nv_bfloat16 g_h2bf[2][4194304];  // conv2 out hi/lo, [bt][qp*256+c] (fc A-ready)
__device__ __nv_bfloat16 g_embbf[2][524288];  // emb hi/lo (expert A-ready)
__device__ float g_fcp[8 * 1024 * 512];       // fc split-K partials
__device__ float g_gw[64 * 6];
__device__ int g_gidx[64 * 6];
__device__ __nv_bfloat16 g_w1bf[2][64][256];     // conv1 W [hi/lo][n][k]
__device__ __nv_bfloat16 g_w2bf[2][256][1024];   // conv2 W [hi/lo][n][k]
__device__ __nv_bfloat16 g_fcwbf[2][512][4096];  // fc W    [hi/lo][n][k]
__device__ __nv_bfloat16 g_ewbf[2][6][512][512]; // expert W [hi/lo][e][n][k]

// ---------------- helpers ----------------
__device__ __forceinline__ int clamp_topk(const int* topk) {
    int k = *topk;
    if (k < 1 || k > 6) {
        float fv = __int_as_float(k);
        if (fv >= 1.0f && fv <= 6.0f) k = (int)fv; else k = 2;
    }
    return k;
}
__device__ __forceinline__ float gelu_exact(float t) {
    return 0.5f * t * (1.0f + erff(t * 0.7071067811865476f));
}
__device__ __forceinline__ uint32_t smem_u32(const void* p) {
    uint32_t a;
    asm("{ .reg .u64 t; cvta.to.shared.u64 t, %1; cvt.u32.u64 %0, t; }" : "=r"(a) : "l"(p));
    return a;
}
__device__ __forceinline__ void ldmx4(uint32_t* r, uint32_t addr) {
    asm volatile("ldmatrix.sync.aligned.m8n8.x4.shared.b16 {%0,%1,%2,%3}, [%4];"
        : "=r"(r[0]), "=r"(r[1]), "=r"(r[2]), "=r"(r[3]) : "r"(addr));
}
__device__ __forceinline__ void ldmx2(uint32_t* r, uint32_t addr) {
    asm volatile("ldmatrix.sync.aligned.m8n8.x2.shared.b16 {%0,%1}, [%2];"
        : "=r"(r[0]), "=r"(r[1]) : "r"(addr));
}
__device__ __forceinline__ void mma16816(float* d, const uint32_t* a, const uint32_t* b) {
    asm volatile("mma.sync.aligned.m16n8k16.row.col.f32.bf16.bf16.f32 "
        "{%0,%1,%2,%3}, {%4,%5,%6,%7}, {%8,%9}, {%0,%1,%2,%3};"
        : "+f"(d[0]), "+f"(d[1]), "+f"(d[2]), "+f"(d[3])
        : "r"(a[0]), "r"(a[1]), "r"(a[2]), "r"(a[3]), "r"(b[0]), "r"(b[1]));
}
__device__ __forceinline__ void cvt4(const float* f, uint2& hi, uint2& lo) {
    union { __nv_bfloat16 b[4]; uint2 u; } H, L;
#pragma unroll
    for (int q = 0; q < 4; q++) {
        H.b[q] = __float2bfloat16(f[q]);
        L.b[q] = __float2bfloat16(f[q] - __bfloat162float(H.b[q]));
    }
    hi = H.u; lo = L.u;
}
__device__ __forceinline__ void cpa16(uint32_t dst, const void* src) {
    asm volatile("cp.async.cg.shared.global [%0], [%1], 16;" :: "r"(dst), "l"(src) : "memory");
}
#define CPA_COMMIT() asm volatile("cp.async.commit_group;" ::: "memory")
#define CPA_WAIT0()  asm volatile("cp.async.wait_group 0;" ::: "memory")
#define CPA_WAIT1()  asm volatile("cp.async.wait_group 1;" ::: "memory")

__device__ __forceinline__ void store_hilo2(__nv_bfloat16* plane_hi, __nv_bfloat16* plane_lo,
                                            size_t off, float o0, float o1) {
    union { __nv_bfloat16 b[2]; uint32_t u; } H, L;
    H.b[0] = __float2bfloat16(o0);
    H.b[1] = __float2bfloat16(o1);
    L.b[0] = __float2bfloat16(o0 - __bfloat162float(H.b[0]));
    L.b[1] = __float2bfloat16(o1 - __bfloat162float(H.b[1]));
    *(uint32_t*)&plane_hi[off] = H.u;
    *(uint32_t*)&plane_lo[off] = L.u;
}

// ---------------- fused weight prep: w1 (64 blk) | w2 (1024 blk) | fcw (2048 blk) | ew (1536 blk) ----------------
__global__ __launch_bounds__(256) void k_prep_all(const float* __restrict__ w1,
                                                  const float* __restrict__ w2,
                                                  const float* __restrict__ fcw,
                                                  const float* __restrict__ ew) {
    __shared__ float ts[32][33];
    int bx = blockIdx.x;
    int tid = threadIdx.x;

    if (bx < 64) {
        // conv1 weights
        int idx = bx * 256 + tid;
        int o = idx >> 8, r = idx & 255;
        int c = r >> 4, i = (r >> 2) & 3, j = r & 3;
        int k = i * 64 + j * 16 + c;
        float f = w1[idx];
        __nv_bfloat16 hi = __float2bfloat16(f);
        g_w1bf[0][o][k] = hi;
        g_w1bf[1][o][k] = __float2bfloat16(f - __bfloat162float(hi));
        return;
    }
    bx -= 64;
    if (bx < 1024) {
        // conv2 weights (gather form)
        int idx = bx * 256 + tid;
        int o = idx >> 10, k = idx & 1023;
        int cin = k & 63, ij = k >> 6;
        float f = w2[o * 1024 + cin * 16 + ij];
        __nv_bfloat16 hi = __float2bfloat16(f);
        g_w2bf[0][o][k] = hi;
        g_w2bf[1][o][k] = __float2bfloat16(f - __bfloat162float(hi));
        return;
    }
    bx -= 1024;
    if (bx < 2048) {
        // fc weights: 32x32 tile transpose
        int kb = (bx >> 4) * 32, nb = (bx & 15) * 32;
#pragma unroll
        for (int it = 0; it < 4; it++) {
            int r = it * 8 + (tid >> 5), c = tid & 31;
            ts[r][c] = fcw[(size_t)(kb + r) * 512 + nb + c];
        }
        __syncthreads();
        int h = tid >> 7, n = (tid >> 2) & 31, q = tid & 3;
        union { __nv_bfloat16 b[8]; uint4 u; } U;
#pragma unroll
        for (int i = 0; i < 8; i++) {
            float f = ts[q * 8 + i][n];
            __nv_bfloat16 hi = __float2bfloat16(f);
            U.b[i] = h ? __float2bfloat16(f - __bfloat162float(hi)) : hi;
        }
        *(uint4*)&g_fcwbf[h][nb + n][kb + q * 8] = U.u;
        return;
    }
    bx -= 2048;
    {
        // expert weights: 32x32 tile transpose per expert (1536 blocks)
        int e = bx >> 8, r2 = bx & 255;
        int kb = (r2 >> 4) * 32, nb = (r2 & 15) * 32;
        const float* we = ew + (size_t)e * 262144;
#pragma unroll
        for (int it = 0; it < 4; it++) {
            int r = it * 8 + (tid >> 5), c = tid & 31;
            ts[r][c] = we[(size_t)(kb + r) * 512 + nb + c];
        }
        __syncthreads();
        int h = tid >> 7, n = (tid >> 2) & 31, q = tid & 3;
        union { __nv_bfloat16 b[8]; uint4 u; } U;
#pragma unroll
        for (int i = 0; i < 8; i++) {
            float f = ts[q * 8 + i][n];
            __nv_bfloat16 hi = __float2bfloat16(f);
            U.b[i] = h ? __float2bfloat16(f - __bfloat162float(hi)) : hi;
        }
        *(uint4*)&g_ewbf[h][e][nb + n][kb + q * 8] = U.u;
    }
}

// ---------------- conv1: M=262144 (tile 256), N=64, K=256 (8 k32 chunks), cp.async pipelined ----------------
#define C1_SMEM 221184
__global__ __launch_bounds__(512, 1) void k_conv1_mma(const float* __restrict__ x,
                                                      const float* __restrict__ cbp,
                                                      const float* __restrict__ lg,
                                                      const float* __restrict__ lb) {
    extern __shared__ __align__(16) unsigned char sm[];
    uint32_t sb = smem_u32(sm);
    int tid = threadIdx.x, lane = tid & 31, wid = tid >> 5;
    int wm = wid >> 1, wn = wid & 1;
    const float* xb = x + (size_t)blockIdx.x * 65536;

#pragma unroll
    for (int it = 0; it < 8; it++) {
        int g = it * 512 + tid;
        int chunk = g >> 10, h = (g >> 9) & 1, rem = g & 511;
        int o = rem >> 3, q = rem & 7;
        uint4 v = *(const uint4*)((const unsigned char*)g_w1bf + h * 32768 + o * 512 + chunk * 128 + q * 16);
        *(uint4*)(sm + 147456 + chunk * 18432 + h * 9216 + o * 144 + q * 16) = v;
    }

#define C1_CPA(kc) do { \
    int i_ = (kc) >> 1, jp = ((kc) & 1) * 2; \
    _Pragma("unroll") \
    for (int it = 0; it < 4; it++) { \
        int g = it * 512 + tid; int m = g >> 3, q = g & 7; \
        int j = jp + (q >> 2), qc = q & 3; \
        cpa16(sb + ((kc) & 1) * 32768 + m * 128 + q * 16, \
              xb + (((m >> 4) * 4 + i_) * 64 + (m & 15) * 4 + j) * 16 + qc * 4); \
    } CPA_COMMIT(); } while (0)

#define C1_CONV(kc) do { \
    _Pragma("unroll") \
    for (int it = 0; it < 4; it++) { \
        int g = it * 512 + tid; int m = g >> 3, q = g & 7; \
        float4 v = *(const float4*)(sm + ((kc) & 1) * 32768 + m * 128 + q * 16); \
        uint2 hi, lo; cvt4((const float*)&v, hi, lo); \
        *(uint2*)(sm + 65536 + ((kc) & 1) * 40960 + m * 80 + q * 8) = hi; \
        *(uint2*)(sm + 65536 + ((kc) & 1) * 40960 + 20480 + m * 80 + q * 8) = lo; \
    } } while (0)

    C1_CPA(0);
    C1_CPA(1);
    CPA_WAIT1();
    C1_CONV(0);
    __syncthreads();

    float acc[2][4][4];
#pragma unroll
    for (int a = 0; a < 2; a++)
#pragma unroll
        for (int b = 0; b < 4; b++)
#pragma unroll
            for (int c = 0; c < 4; c++) acc[a][b][c] = 0.0f;

    for (int kc = 0; kc < 8; kc++) {
        if (kc < 6) C1_CPA(kc + 2);
        if (kc < 7) {
            if (kc < 6) CPA_WAIT1(); else CPA_WAIT0();
            C1_CONV(kc + 1);
        }
        uint32_t aHi = sb + 65536 + (kc & 1) * 40960 + (wm * 32 + (lane & 15)) * 80 + (lane >> 4) * 16;
        uint32_t bB = sb + 147456 + (kc >> 1) * 18432 + (wn * 32 + (lane & 7)) * 144 + ((lane >> 3) & 1) * 16;
#pragma unroll
        for (int ks = 0; ks < 2; ks++) {
            int ks2 = (kc & 1) * 2 + ks;
            uint32_t ah[2][4], al[2][4];
            ldmx4(ah[0], aHi + ks * 32);
            ldmx4(ah[1], aHi + 1280 + ks * 32);
            ldmx4(al[0], aHi + 20480 + ks * 32);
            ldmx4(al[1], aHi + 20480 + 1280 + ks * 32);
#pragma unroll
            for (int nt = 0; nt < 4; nt++) {
                uint32_t bh[2], bl[2];
                ldmx2(bh, bB + nt * 1152 + ks2 * 32);
                ldmx2(bl, bB + 9216 + nt * 1152 + ks2 * 32);
#pragma unroll
                for (int mt = 0; mt < 2; mt++) {
                    mma16816(acc[mt][nt], ah[mt], bh);
                    mma16816(acc[mt][nt], ah[mt], bl);
                    mma16816(acc[mt][nt], al[mt], bh);
                }
            }
        }
        __syncthreads();
    }

    float* red = (float*)sm;
    int r0 = lane >> 2, cbs = (lane & 3) * 2;
#pragma unroll
    for (int mt = 0; mt < 2; mt++)
#pragma unroll
        for (int half = 0; half < 2; half++) {
            float s = 0.0f, s2 = 0.0f;
#pragma unroll
            for (int nt = 0; nt < 4; nt++)
#pragma unroll
                for (int c = 0; c < 2; c++) {
                    int col = wn * 32 + nt * 8 + cbs + c;
                    float t = acc[mt][nt][half * 2 + c] + cbp[col];
                    acc[mt][nt][half * 2 + c] = t;
                    s += t; s2 += t * t;
                }
            s += __shfl_xor_sync(0xffffffffu, s, 1);
            s += __shfl_xor_sync(0xffffffffu, s, 2);
            s2 += __shfl_xor_sync(0xffffffffu, s2, 1);
            s2 += __shfl_xor_sync(0xffffffffu, s2, 2);
            int row = wm * 32 + mt * 16 + half * 8 + r0;
            if ((lane & 3) == 0) {
                red[row * 4 + wn * 2 + 0] = s;
                red[row * 4 + wn * 2 + 1] = s2;
            }
        }
    __syncthreads();
#pragma unroll
    for (int mt = 0; mt < 2; mt++)
#pragma unroll
        for (int half = 0; half < 2; half++) {
            int row = wm * 32 + mt * 16 + half * 8 + r0;
            float s = red[row * 4 + 0] + red[row * 4 + 2];
            float s2 = red[row * 4 + 1] + red[row * 4 + 3];
            float mean = s * (1.0f / 64.0f);
            float var = s2 * (1.0f / 64.0f) - mean * mean;
            float rstd = rsqrtf(var + 1e-5f);
            int ph = row >> 4, pw = row & 15;
            size_t base = (((size_t)blockIdx.x * 16 + (ph >> 2) * 4 + (pw >> 2)) * 16 +
                           ((ph & 3) * 4 + (pw & 3))) * 64;
#pragma unroll
            for (int nt = 0; nt < 4; nt++) {
                int col = wn * 32 + nt * 8 + cbs;
                float o0 = gelu_exact((acc[mt][nt][half * 2 + 0] - mean) * rstd * lg[col] + lb[col]);
                float o1 = gelu_exact((acc[mt][nt][half * 2 + 1] - mean) * rstd * lg[col + 1] + lb[col + 1]);
                store_hilo2(g_h1bf[0], g_h1bf[1], base + col, o0, o1);
            }
        }
}

// ---------------- conv2: M=16384 (tile 128), N=256, K=1024, A+B both cp.async ----------------
#define C2_SMEM 221184
__global__ __launch_bounds__(256) void k_conv2_mma(const float* __restrict__ cbp,
                                                   const float* __restrict__ lg,
                                                   const float* __restrict__ lb) {
    extern __shared__ __align__(16) unsigned char sm[];
    uint32_t sb = smem_u32(sm);
    int tid = threadIdx.x, lane = tid & 31, wid = tid >> 5;
    int wm = wid & 3, wn = wid >> 2;
    int p0 = blockIdx.x * 128;

#define C2_CP_A(kc, buf) do { \
    _Pragma("unroll") \
    for (int it = 0; it < 8; it++) { \
        int g = it * 256 + tid; int h = g >> 10, rem = g & 1023; \
        int n = rem >> 3, q = rem & 7; \
        cpa16(sb + (buf) * 36864 + h * 18432 + n * 144 + q * 16, \
              g_h1bf[0] + (size_t)h * 16777216 + ((size_t)(p0 + n) * 16 + (kc)) * 64 + q * 8); \
    } } while (0)

#define C2_CP_B(kc, buf) do { \
    _Pragma("unroll") \
    for (int it = 0; it < 16; it++) { \
        int g = it * 256 + tid; int h = g >> 11, rem = g & 2047; \
        int n = rem >> 3, q = rem & 7; \
        cpa16(sb + 73728 + (buf) * 73728 + h * 36864 + n * 144 + q * 16, \
              (const unsigned char*)g_w2bf + h * 524288 + n * 2048 + (kc) * 128 + q * 16); \
    } } while (0)

    C2_CP_A(0, 0);
    C2_CP_B(0, 0);
    CPA_COMMIT();
    CPA_WAIT0();
    __syncthreads();

    float acc[2][16][4];
#pragma unroll
    for (int a = 0; a < 2; a++)
#pragma unroll
        for (int b = 0; b < 16; b++)
#pragma unroll
            for (int c = 0; c < 4; c++) acc[a][b][c] = 0.0f;

    for (int kc = 0; kc < 16; kc++) {
        if (kc < 15) {
            C2_CP_A(kc + 1, (kc + 1) & 1);
            C2_CP_B(kc + 1, (kc + 1) & 1);
            CPA_COMMIT();
        }
        uint32_t aHi = sb + (kc & 1) * 36864 + (wm * 32 + (lane & 15)) * 144 + (lane >> 4) * 16;
        uint32_t bB = sb + 73728 + (kc & 1) * 73728 + (wn * 128 + (lane & 7)) * 144 + ((lane >> 3) & 1) * 16;
#pragma unroll
        for (int ks = 0; ks < 4; ks++) {
            uint32_t ah[2][4], al[2][4];
            ldmx4(ah[0], aHi + ks * 32);
            ldmx4(ah[1], aHi + 2304 + ks * 32);
            ldmx4(al[0], aHi + 18432 + ks * 32);
            ldmx4(al[1], aHi + 18432 + 2304 + ks * 32);
#pragma unroll
            for (int nt = 0; nt < 16; nt++) {
                uint32_t bh[2], bl[2];
                ldmx2(bh, bB + nt * 1152 + ks * 32);
                ldmx2(bl, bB + 36864 + nt * 1152 + ks * 32);
#pragma unroll
                for (int mt = 0; mt < 2; mt++) {
                    mma16816(acc[mt][nt], ah[mt], bh);
                    mma16816(acc[mt][nt], ah[mt], bl);
                    mma16816(acc[mt][nt], al[mt], bh);
                }
            }
        }
        if (kc < 15) {
            CPA_WAIT0();
            __syncthreads();
        }
    }
    __syncthreads();

    float* red = (float*)sm;
    int r0 = lane >> 2, cbs = (lane & 3) * 2;
#pragma unroll
    for (int mt = 0; mt < 2; mt++)
#pragma unroll
        for (int half = 0; half < 2; half++) {
            float s = 0.0f, s2 = 0.0f;
#pragma unroll
            for (int nt = 0; nt < 16; nt++)
#pragma unroll
                for (int c = 0; c < 2; c++) {
                    int col = wn * 128 + nt * 8 + cbs + c;
                    float t = acc[mt][nt][half * 2 + c] + cbp[col];
                    acc[mt][nt][half * 2 + c] = t;
                    s += t; s2 += t * t;
                }
            s += __shfl_xor_sync(0xffffffffu, s, 1);
            s += __shfl_xor_sync(0xffffffffu, s, 2);
            s2 += __shfl_xor_sync(0xffffffffu, s2, 1);
            s2 += __shfl_xor_sync(0xffffffffu, s2, 2);
            int row = wm * 32 + mt * 16 + half * 8 + r0;
            if ((lane & 3) == 0) {
                red[row * 4 + wn * 2 + 0] = s;
                red[row * 4 + wn * 2 + 1] = s2;
            }
        }
    __syncthreads();
#pragma unroll
    for (int mt = 0; mt < 2; mt++)
#pragma unroll
        for (int half = 0; half < 2; half++) {
            int row = wm * 32 + mt * 16 + half * 8 + r0;
            float s = red[row * 4 + 0] + red[row * 4 + 2];
            float s2 = red[row * 4 + 1] + red[row * 4 + 3];
            float mean = s * (1.0f / 256.0f);
            float var = s2 * (1.0f / 256.0f) - mean * mean;
            float rstd = rsqrtf(var + 1e-5f);
            size_t base = (size_t)(p0 + row) * 256;
#pragma unroll
            for (int nt = 0; nt < 16; nt++) {
                int col = wn * 128 + nt * 8 + cbs;
                float o0 = gelu_exact((acc[mt][nt][half * 2 + 0] - mean) * rstd * lg[col] + lb[col]);
                float o1 = gelu_exact((acc[mt][nt][half * 2 + 1] - mean) * rstd * lg[col + 1] + lb[col + 1]);
                store_hilo2(g_h2bf[0], g_h2bf[1], base + col, o0, o1);
            }
        }
}

// ---------------- fc: M=1024 (tile 128), N=512 (tile 128), K=4096 splitK=8, A+B cp.async ----------------
#define FC_SMEM 147456
__global__ __launch_bounds__(256) void k_fc_mma() {
    extern __shared__ __align__(16) unsigned char sm[];
    uint32_t sb = smem_u32(sm);
    int tid = threadIdx.x, lane = tid & 31, wid = tid >> 5;
    int wm = wid & 3, wn = wid >> 2;
    int n0 = blockIdx.x * 128;
    int m0 = blockIdx.y * 128;
    int z = blockIdx.z;

#define FC_CP_A(kc, buf) do { \
    _Pragma("unroll") \
    for (int it = 0; it < 8; it++) { \
        int g = it * 256 + tid; int h = g >> 10, rem = g & 1023; \
        int m = rem >> 3, q = rem & 7; \
        cpa16(sb + (buf) * 36864 + h * 18432 + m * 144 + q * 16, \
              g_h2bf[0] + (size_t)h * 4194304 + (size_t)(m0 + m) * 4096 + z * 512 + (kc) * 64 + q * 8); \
    } } while (0)

#define FC_CP_B(kc, buf) do { \
    _Pragma("unroll") \
    for (int it = 0; it < 8; it++) { \
        int g = it * 256 + tid; int h = g >> 10, rem = g & 1023; \
        int n = rem >> 3, q = rem & 7; \
        cpa16(sb + 73728 + (buf) * 36864 + h * 18432 + n * 144 + q * 16, \
              (const unsigned char*)g_fcwbf + h * 4194304 + (size_t)(n0 + n) * 8192 + (z * 512 + (kc) * 64) * 2 + q * 16); \
    } } while (0)

    FC_CP_A(0, 0);
    FC_CP_B(0, 0);
    CPA_COMMIT();
    CPA_WAIT0();
    __syncthreads();

    float acc[2][8][4];
#pragma unroll
    for (int a = 0; a < 2; a++)
#pragma unroll
        for (int b = 0; b < 8; b++)
#pragma unroll
            for (int c = 0; c < 4; c++) acc[a][b][c] = 0.0f;

    for (int kc = 0; kc < 8; kc++) {
        if (kc < 7) {
            FC_CP_A(kc + 1, (kc + 1) & 1);
            FC_CP_B(kc + 1, (kc + 1) & 1);
            CPA_COMMIT();
        }
        uint32_t aHi = sb + (kc & 1) * 36864 + (wm * 32 + (lane & 15)) * 144 + (lane >> 4) * 16;
        uint32_t bB = sb + 73728 + (kc & 1) * 36864 + (wn * 64 + (lane & 7)) * 144 + ((lane >> 3) & 1) * 16;
#pragma unroll
        for (int ks = 0; ks < 4; ks++) {
            uint32_t ah[2][4], al[2][4];
            ldmx4(ah[0], aHi + ks * 32);
            ldmx4(ah[1], aHi + 2304 + ks * 32);
            ldmx4(al[0], aHi + 18432 + ks * 32);
            ldmx4(al[1], aHi + 18432 + 2304 + ks * 32);
#pragma unroll
            for (int nt = 0; nt < 8; nt++) {
                uint32_t bh[2], bl[2];
                ldmx2(bh, bB + nt * 1152 + ks * 32);
                ldmx2(bl, bB + 18432 + nt * 1152 + ks * 32);
#pragma unroll
                for (int mt = 0; mt < 2; mt++) {
                    mma16816(acc[mt][nt], ah[mt], bh);
                    mma16816(acc[mt][nt], ah[mt], bl);
                    mma16816(acc[mt][nt], al[mt], bh);
                }
            }
        }
        if (kc < 7) {
            CPA_WAIT0();
            __syncthreads();
        }
    }

    int r0 = lane >> 2, cbs = (lane & 3) * 2;
#pragma unroll
    for (int mt = 0; mt < 2; mt++)
#pragma unroll
        for (int half = 0; half < 2; half++) {
            int row = m0 + wm * 32 + mt * 16 + half * 8 + r0;
#pragma unroll
            for (int nt = 0; nt < 8; nt++)
#pragma unroll
                for (int c = 0; c < 2; c++) {
                    int col = n0 + wn * 64 + nt * 8 + cbs + c;
                    g_fcp[(size_t)z * 524288 + (size_t)row * 512 + col] = acc[mt][nt][half * 2 + c];
                }
        }
}

// ---------------- gating (fused split-K reduce + bf16 emb emit + DFT top-k) ----------------
__global__ __launch_bounds__(512) void k_gate(const float* __restrict__ fcb,
                                              const float* __restrict__ wg,
                                              const int* __restrict__ topk) {
    int b = blockIdx.x;
    int d = threadIdx.x;
    float bias = fcb[d];
    float xv[16];
#pragma unroll
    for (int t = 0; t < 16; t++) {
        size_t off = (size_t)(b * 16 + t) * 512 + d;
        float s = bias;
#pragma unroll
        for (int z = 0; z < 8; z++) s += g_fcp[(size_t)z * 524288 + off];
        xv[t] = s;
        __nv_bfloat16 hi = __float2bfloat16(s);
        g_embbf[0][off] = hi;
        g_embbf[1][off] = __float2bfloat16(s - __bfloat162float(hi));
    }

    float cs[16], sn[16];
#pragma unroll
    for (int i = 0; i < 16; i++) {
        float th = 6.283185307179586f * (float)i * (1.0f / 16.0f);
        sincosf(th, &sn[i], &cs[i]);
    }
    float amp[8];
#pragma unroll
    for (int f = 1; f <= 8; f++) {
        float re = 0.0f, im = 0.0f;
#pragma unroll
        for (int t = 0; t < 16; t++) {
            int id = (f * t) & 15;
            re += xv[t] * cs[id];
            im -= xv[t] * sn[id];
        }
        amp[f - 1] = sqrtf(re * re + im * im) * 0.25f;
    }
    __shared__ float red[16][8];
    int lane = d & 31, w = d >> 5;
#pragma unroll
    for (int f = 0; f < 8; f++) {
#pragma unroll
        for (int o = 1; o < 32; o <<= 1) amp[f] += __shfl_xor_sync(0xffffffffu, amp[f], o);
    }
    if (lane == 0)
#pragma unroll
        for (int f = 0; f < 8; f++) red[w][f] = amp[f];
    __syncthreads();
    if (d == 0) {
        float am[8];
#pragma unroll
        for (int f = 0; f < 8; f++) {
            float s = 0.0f;
            for (int ww = 0; ww < 16; ww++) s += red[ww][f];
            am[f] = s * (1.0f / 512.0f);
        }
        float lgt[6];
#pragma unroll
        for (int e = 0; e < 6; e++) {
            float s = 0.0f;
#pragma unroll
            for (int f = 0; f < 8; f++) s += am[f] * wg[f * 6 + e];
            lgt[e] = s;
        }
        int k = clamp_topk(topk);
        bool used[6] = {false, false, false, false, false, false};
        int sel[6]; float sw[6];
        for (int kk = 0; kk < k; kk++) {
            float best = -1e30f; int bi = 0;
            for (int e = 0; e < 6; e++)
                if (!used[e] && lgt[e] > best) { best = lgt[e]; bi = e; }
            used[bi] = true; sel[kk] = bi; sw[kk] = best;
        }
        float mx = sw[0], ssum = 0.0f;
        for (int kk = 0; kk < k; kk++) { sw[kk] = expf(sw[kk] - mx); ssum += sw[kk]; }
        for (int kk = 0; kk < k; kk++) {
            g_gw[b * 6 + kk] = sw[kk] / ssum;
            g_gidx[b * 6 + kk] = sel[kk];
        }
    }
}

// ---------------- experts via MMA: k32 chunks (16 iters), A via cp.async from g_embbf ----------------
#define EXP_SMEM 115200
__global__ __launch_bounds__(256) void k_expert_mma(const float* __restrict__ eb,
                                                    const int* __restrict__ topk,
                                                    float* __restrict__ out) {
    extern __shared__ __align__(16) unsigned char sm[];
    uint32_t sb = smem_u32(sm);
    int tid = threadIdx.x, lane = tid & 31, wid = tid >> 5;
    int b = blockIdx.y;
    int nbase = blockIdx.x * 256;
    int k = clamp_topk(topk);

#pragma unroll
    for (int it = 0; it < 8; it++) {
        int g = it * 256 + tid;
        int h = g >> 10, rem = g & 1023;
        int m = rem >> 6, q = rem & 63;
        cpa16(sb + h * 16640 + m * 1040 + q * 16,
              g_embbf[h] + (size_t)(b * 16 + m) * 512 + q * 8);
    }
    CPA_COMMIT();

#define EXP_CP_B(e, kc, buf) do { \
    _Pragma("unroll") \
    for (int it = 0; it < 8; it++) { \
        int g = it * 256 + tid; int h = g >> 10, rem = g & 1023; \
        int n = rem >> 2, part = rem & 3; \
        cpa16(sb + 33280 + (buf) * 40960 + h * 20480 + n * 80 + part * 16, \
              (const unsigned char*)g_ewbf + ((size_t)(h * 6 + (e)) * 512 + nbase + n) * 1024 + (kc) * 64 + part * 16); \
    } CPA_COMMIT(); } while (0)

    float comb[4][4];
#pragma unroll
    for (int nt = 0; nt < 4; nt++)
#pragma unroll
        for (int j = 0; j < 4; j++) comb[nt][j] = 0.0f;

    for (int ke = 0; ke < k; ke++) {
        int e = g_gidx[b * 6 + ke];
        float gv = g_gw[b * 6 + ke];

        EXP_CP_B(e, 0, 0);
        CPA_WAIT0();
        __syncthreads();

        float acc[4][4];
#pragma unroll
        for (int nt = 0; nt < 4; nt++)
#pragma unroll
            for (int j = 0; j < 4; j++) acc[nt][j] = 0.0f;

        for (int kc = 0; kc < 16; kc++) {
            if (kc < 15) EXP_CP_B(e, kc + 1, (kc + 1) & 1);
#pragma unroll
            for (int ks = 0; ks < 2; ks++) {
                uint32_t aOff = sb + (lane & 15) * 1040 + (lane >> 4) * 16 + kc * 64 + ks * 32;
                uint32_t ah[4], al[4];
                ldmx4(ah, aOff);
                ldmx4(al, aOff + 16640);
                uint32_t bB = sb + 33280 + (kc & 1) * 40960 + (wid * 32 + (lane & 7)) * 80 +
                              ((lane >> 3) & 1) * 16 + ks * 32;
#pragma unroll
                for (int nt = 0; nt < 4; nt++) {
                    uint32_t bh[2], bl[2];
                    ldmx2(bh, bB + nt * 640);
                    ldmx2(bl, bB + 20480 + nt * 640);
                    mma16816(acc[nt], ah, bh);
                    mma16816(acc[nt], ah, bl);
                    mma16816(acc[nt], al, bh);
                }
            }
            if (kc < 15) {
                CPA_WAIT0();
                __syncthreads();
            }
        }

#pragma unroll
        for (int nt = 0; nt < 4; nt++)
#pragma unroll
            for (int j = 0; j < 4; j++) {
                int col = nbase + wid * 32 + nt * 8 + (lane & 3) * 2 + (j & 1);
                float y = acc[nt][j] + eb[e * 512 + col];
                comb[nt][j] += gv * __expf(y);
            }
    }

#pragma unroll
    for (int nt = 0; nt < 4; nt++)
#pragma unroll
        for (int j = 0; j < 4; j++) {
            int col = nbase + wid * 32 + nt * 8 + (lane & 3) * 2 + (j & 1);
            int row = b * 16 + (lane >> 2) + (j >> 1) * 8;
            float c = comb[nt][j];
            if (c == 0.0f) c = LOG_EPS;
            out[(size_t)row * 512 + col] = __logf(c);
        }
}

// ---------------- launch ----------------
extern "C" void kernel_launch(void* const* d_in, const int* in_sizes, int n_in,
                              void* d_out, int out_size) {
    const float* x   = (const float*)d_in[0];
    const float* w1  = (const float*)d_in[1];
    const float* b1  = (const float*)d_in[2];
    const float* g1  = (const float*)d_in[3];
    const float* be1 = (const float*)d_in[4];
    const float* w2  = (const float*)d_in[5];
    const float* b2  = (const float*)d_in[6];
    const float* g2  = (const float*)d_in[7];
    const float* be2 = (const float*)d_in[8];
    const float* fcw = (const float*)d_in[9];
    const float* fcb = (const float*)d_in[10];
    const float* wg  = (const float*)d_in[11];
    const float* ew  = (const float*)d_in[12];
    const float* ebp = (const float*)d_in[13];
    const int* topk  = (const int*)d_in[14];
    float* out = (float*)d_out;

    cudaFuncSetAttribute(k_conv1_mma, cudaFuncAttributeMaxDynamicSharedMemorySize, C1_SMEM);
    cudaFuncSetAttribute(k_conv2_mma, cudaFuncAttributeMaxDynamicSharedMemorySize, C2_SMEM);
    cudaFuncSetAttribute(k_fc_mma, cudaFuncAttributeMaxDynamicSharedMemorySize, FC_SMEM);
    cudaFuncSetAttribute(k_expert_mma, cudaFuncAttributeMaxDynamicSharedMemorySize, EXP_SMEM);

    k_prep_all<<<4672, 256>>>(w1, w2, fcw, ew);
    k_conv1_mma<<<1024, 512, C1_SMEM>>>(x, b1, g1, be1);
    k_conv2_mma<<<128, 256, C2_SMEM>>>(b2, g2, be2);
    dim3 gfc(4, 8, 8);
    k_fc_mma<<<gfc, 256, FC_SMEM>>>();
    k_gate<<<64, 512>>>(fcb, wg, topk);
    dim3 ge(2, 64);
    k_expert_mma<<<ge, 256, EXP_SMEM>>>(ebp, topk, out);
}